// round 1
// baseline (speedup 1.0000x reference)
#include <cuda_runtime.h>

#define BATCH 4
#define SEQ   2048
#define CH    1024
#define NHEAD 16
#define HDIM  64
#define PAD   68   // smem row stride (floats): 16B-aligned, low-conflict

// Scratch (allocation-free rule: __device__ globals)
__device__ float g_q[BATCH * NHEAD * HDIM * SEQ];   // [b,h,d,t]
__device__ float g_k[BATCH * NHEAD * HDIM * SEQ];   // [b,h,d,t]
__device__ float g_v[BATCH * NHEAD * SEQ * HDIM];   // [b,h,t,d]
__device__ float g_att[BATCH * SEQ * CH];           // [b,t,c]

// ---------------------------------------------------------------------------
// Kernel 1: QKV GEMM  Y[8192, 3072] = X[8192,1024] @ W[1024,3072] + b
// 128x128 tile, BK=16, 256 threads, 8x8 microtile.
// Epilogue scatters into q/k ([b,h,d,t]) and v ([b,h,t,d]).
// ---------------------------------------------------------------------------
__global__ __launch_bounds__(256) void qkv_gemm_kernel(
    const float* __restrict__ X, const float* __restrict__ W,
    const float* __restrict__ bias)
{
    __shared__ float As[16][128];
    __shared__ float Bs[16][128];
    const int tid = threadIdx.x;
    const int tx = tid & 15;
    const int ty = tid >> 4;
    const int m0 = blockIdx.y * 128;
    const int n0 = blockIdx.x * 128;
    const int N = 3 * CH;

    float acc[8][8];
#pragma unroll
    for (int i = 0; i < 8; i++)
#pragma unroll
        for (int j = 0; j < 8; j++) acc[i][j] = 0.f;

    for (int k0 = 0; k0 < CH; k0 += 16) {
#pragma unroll
        for (int it = 0; it < 2; it++) {
            int idx = it * 256 + tid;
            int row = idx >> 2;
            int cg  = (idx & 3) * 4;
            float4 a = *reinterpret_cast<const float4*>(X + (m0 + row) * CH + k0 + cg);
            As[cg + 0][row] = a.x;
            As[cg + 1][row] = a.y;
            As[cg + 2][row] = a.z;
            As[cg + 3][row] = a.w;
        }
#pragma unroll
        for (int it = 0; it < 2; it++) {
            int idx = it * 256 + tid;
            int row = idx >> 5;
            int cg  = (idx & 31) * 4;
            *reinterpret_cast<float4*>(&Bs[row][cg]) =
                *reinterpret_cast<const float4*>(W + (k0 + row) * N + n0 + cg);
        }
        __syncthreads();
#pragma unroll
        for (int k = 0; k < 16; k++) {
            float ar[8], br[8];
            *reinterpret_cast<float4*>(&ar[0]) = *reinterpret_cast<float4*>(&As[k][ty * 8]);
            *reinterpret_cast<float4*>(&ar[4]) = *reinterpret_cast<float4*>(&As[k][ty * 8 + 4]);
            *reinterpret_cast<float4*>(&br[0]) = *reinterpret_cast<float4*>(&Bs[k][tx * 8]);
            *reinterpret_cast<float4*>(&br[4]) = *reinterpret_cast<float4*>(&Bs[k][tx * 8 + 4]);
#pragma unroll
            for (int i = 0; i < 8; i++)
#pragma unroll
                for (int j = 0; j < 8; j++)
                    acc[i][j] = fmaf(ar[i], br[j], acc[i][j]);
        }
        __syncthreads();
    }

    const int mbase = m0 + ty * 8;
    const int b  = mbase >> 11;          // / SEQ
    const int t0 = mbase & (SEQ - 1);
    const int nbase = n0 + tx * 8;
    const int sec = n0 >> 10;            // 0=q 1=k 2=v (tile never straddles)

    if (sec < 2) {
        float* dst = (sec == 0) ? g_q : g_k;
#pragma unroll
        for (int j = 0; j < 8; j++) {
            int n1 = (nbase + j) & (CH - 1);
            int h = n1 >> 6, d = n1 & 63;
            float bv = bias[nbase + j];
            float4 v0 = make_float4(acc[0][j] + bv, acc[1][j] + bv,
                                    acc[2][j] + bv, acc[3][j] + bv);
            float4 v1 = make_float4(acc[4][j] + bv, acc[5][j] + bv,
                                    acc[6][j] + bv, acc[7][j] + bv);
            float* p = dst + ((size_t)((b * NHEAD + h) * HDIM + d)) * SEQ + t0;
            *reinterpret_cast<float4*>(p)     = v0;
            *reinterpret_cast<float4*>(p + 4) = v1;
        }
    } else {
        int n1 = nbase & (CH - 1);
        int h = n1 >> 6, d = n1 & 63;
        float bv[8];
#pragma unroll
        for (int j = 0; j < 8; j++) bv[j] = bias[nbase + j];
#pragma unroll
        for (int i = 0; i < 8; i++) {
            float4 v0 = make_float4(acc[i][0] + bv[0], acc[i][1] + bv[1],
                                    acc[i][2] + bv[2], acc[i][3] + bv[3]);
            float4 v1 = make_float4(acc[i][4] + bv[4], acc[i][5] + bv[5],
                                    acc[i][6] + bv[6], acc[i][7] + bv[7]);
            float* p = g_v + ((size_t)((b * NHEAD + h) * SEQ + (t0 + i))) * HDIM + d;
            *reinterpret_cast<float4*>(p)     = v0;
            *reinterpret_cast<float4*>(p + 4) = v1;
        }
    }
}

// ---------------------------------------------------------------------------
// Kernel 2: causal flash attention, fp32.
// Block = (qtile 64 rows) x (one b,h). 256 threads, 16x16 grid, 4x4 microtile.
// Q,K read from [b,h,d,t] layout -> smem [d][t] tiles, conflict-free float4.
// Online softmax with per-row state in registers (rows map to half-warp).
// ---------------------------------------------------------------------------
__global__ __launch_bounds__(256) void attn_kernel()
{
    extern __shared__ float sm[];
    float* Qs = sm;                    // [64][PAD]  (d-major)
    float* Ks = sm + 64 * PAD;         // [64][PAD]  (d-major)
    float* Vs = sm + 2 * 64 * PAD;     // [64][PAD]  (kv-major)
    float* Pt = sm + 3 * 64 * PAD;     // [64][PAD]  P^T: [kv][q]

    const int tid = threadIdx.x;
    const int tx = tid & 15;
    const int ty = tid >> 4;
    const int qt = (int)gridDim.x - 1 - (int)blockIdx.x;  // big tiles first
    const int bh = blockIdx.y;
    const int q0 = qt * 64;

    const float* qp = g_q + (size_t)bh * HDIM * SEQ;
    const float* kp = g_k + (size_t)bh * HDIM * SEQ;
    const float* vp = g_v + (size_t)bh * SEQ * HDIM;

    // Load Q tile (scaled): Qs[d][r] = q[d][q0+r] * HD^-0.5
#pragma unroll
    for (int it = 0; it < 4; it++) {
        int idx = it * 256 + tid;
        int d = idx >> 4;
        int rg = (idx & 15) * 4;
        float4 v = *reinterpret_cast<const float4*>(qp + (size_t)d * SEQ + q0 + rg);
        v.x *= 0.125f; v.y *= 0.125f; v.z *= 0.125f; v.w *= 0.125f;
        *reinterpret_cast<float4*>(&Qs[d * PAD + rg]) = v;
    }

    float m_i[4] = {-1e30f, -1e30f, -1e30f, -1e30f};
    float l_i[4] = {0.f, 0.f, 0.f, 0.f};
    float o[4][4] = {};

    for (int kt = 0; kt <= qt; kt++) {
        const int k0 = kt * 64;
        __syncthreads();  // protect Ks/Vs/Pt from previous iteration readers
#pragma unroll
        for (int it = 0; it < 4; it++) {
            int idx = it * 256 + tid;
            int d = idx >> 4;
            int rg = (idx & 15) * 4;
            *reinterpret_cast<float4*>(&Ks[d * PAD + rg]) =
                *reinterpret_cast<const float4*>(kp + (size_t)d * SEQ + k0 + rg);
            // reuse idx split for V: r = d, dg = rg
            *reinterpret_cast<float4*>(&Vs[d * PAD + rg]) =
                *reinterpret_cast<const float4*>(vp + (size_t)(k0 + d) * HDIM + rg);
        }
        __syncthreads();

        // S = Qtile @ Ktile^T   (4x4 per thread)
        float s[4][4] = {};
#pragma unroll 8
        for (int d = 0; d < 64; d++) {
            float qa[4], ka[4];
            *reinterpret_cast<float4*>(qa) = *reinterpret_cast<float4*>(&Qs[d * PAD + ty * 4]);
            *reinterpret_cast<float4*>(ka) = *reinterpret_cast<float4*>(&Ks[d * PAD + tx * 4]);
#pragma unroll
            for (int i = 0; i < 4; i++)
#pragma unroll
                for (int j = 0; j < 4; j++)
                    s[i][j] = fmaf(qa[i], ka[j], s[i][j]);
        }

        if (kt == qt) {  // causal mask on diagonal tile
#pragma unroll
            for (int i = 0; i < 4; i++)
#pragma unroll
                for (int j = 0; j < 4; j++)
                    if (tx * 4 + j > ty * 4 + i) s[i][j] = -1e30f;
        }

        // Online softmax; row q = ty*4+i lives on the 16 lanes sharing ty.
#pragma unroll
        for (int i = 0; i < 4; i++) {
            float rm = fmaxf(fmaxf(s[i][0], s[i][1]), fmaxf(s[i][2], s[i][3]));
#pragma unroll
            for (int w = 8; w >= 1; w >>= 1)
                rm = fmaxf(rm, __shfl_xor_sync(0xffffffffu, rm, w));
            float mn = fmaxf(m_i[i], rm);
            float corr = __expf(m_i[i] - mn);
            m_i[i] = mn;
            float rs = 0.f;
#pragma unroll
            for (int j = 0; j < 4; j++) {
                s[i][j] = __expf(s[i][j] - mn);
                rs += s[i][j];
            }
#pragma unroll
            for (int w = 8; w >= 1; w >>= 1)
                rs += __shfl_xor_sync(0xffffffffu, rs, w);
            l_i[i] = l_i[i] * corr + rs;
#pragma unroll
            for (int j = 0; j < 4; j++) o[i][j] *= corr;
        }

        // Write P^T for the PV GEMM
#pragma unroll
        for (int j = 0; j < 4; j++)
#pragma unroll
            for (int i = 0; i < 4; i++)
                Pt[(tx * 4 + j) * PAD + ty * 4 + i] = s[i][j];
        __syncthreads();

        // O += P @ V   (inner dim = kv)
#pragma unroll 8
        for (int kk = 0; kk < 64; kk++) {
            float pa[4], va[4];
            *reinterpret_cast<float4*>(pa) = *reinterpret_cast<float4*>(&Pt[kk * PAD + ty * 4]);
            *reinterpret_cast<float4*>(va) = *reinterpret_cast<float4*>(&Vs[kk * PAD + tx * 4]);
#pragma unroll
            for (int i = 0; i < 4; i++)
#pragma unroll
                for (int j = 0; j < 4; j++)
                    o[i][j] = fmaf(pa[i], va[j], o[i][j]);
        }
    }

    // Normalize and store to [b,t,c]
    const int b = bh >> 4, h = bh & 15;
#pragma unroll
    for (int i = 0; i < 4; i++) {
        float inv = 1.0f / l_i[i];
        float4 ov = make_float4(o[i][0] * inv, o[i][1] * inv,
                                o[i][2] * inv, o[i][3] * inv);
        *reinterpret_cast<float4*>(
            &g_att[(size_t)(b * SEQ + q0 + ty * 4 + i) * CH + h * 64 + tx * 4]) = ov;
    }
}

// ---------------------------------------------------------------------------
// Kernel 3: output projection  out[8192,1024] = g_att @ Wp + bp
// ---------------------------------------------------------------------------
__global__ __launch_bounds__(256) void proj_gemm_kernel(
    const float* __restrict__ W, const float* __restrict__ bias,
    float* __restrict__ out)
{
    __shared__ float As[16][128];
    __shared__ float Bs[16][128];
    const int tid = threadIdx.x;
    const int tx = tid & 15;
    const int ty = tid >> 4;
    const int m0 = blockIdx.y * 128;
    const int n0 = blockIdx.x * 128;
    const float* X = g_att;

    float acc[8][8];
#pragma unroll
    for (int i = 0; i < 8; i++)
#pragma unroll
        for (int j = 0; j < 8; j++) acc[i][j] = 0.f;

    for (int k0 = 0; k0 < CH; k0 += 16) {
#pragma unroll
        for (int it = 0; it < 2; it++) {
            int idx = it * 256 + tid;
            int row = idx >> 2;
            int cg  = (idx & 3) * 4;
            float4 a = *reinterpret_cast<const float4*>(X + (size_t)(m0 + row) * CH + k0 + cg);
            As[cg + 0][row] = a.x;
            As[cg + 1][row] = a.y;
            As[cg + 2][row] = a.z;
            As[cg + 3][row] = a.w;
        }
#pragma unroll
        for (int it = 0; it < 2; it++) {
            int idx = it * 256 + tid;
            int row = idx >> 5;
            int cg  = (idx & 31) * 4;
            *reinterpret_cast<float4*>(&Bs[row][cg]) =
                *reinterpret_cast<const float4*>(W + (size_t)(k0 + row) * CH + n0 + cg);
        }
        __syncthreads();
#pragma unroll
        for (int k = 0; k < 16; k++) {
            float ar[8], br[8];
            *reinterpret_cast<float4*>(&ar[0]) = *reinterpret_cast<float4*>(&As[k][ty * 8]);
            *reinterpret_cast<float4*>(&ar[4]) = *reinterpret_cast<float4*>(&As[k][ty * 8 + 4]);
            *reinterpret_cast<float4*>(&br[0]) = *reinterpret_cast<float4*>(&Bs[k][tx * 8]);
            *reinterpret_cast<float4*>(&br[4]) = *reinterpret_cast<float4*>(&Bs[k][tx * 8 + 4]);
#pragma unroll
            for (int i = 0; i < 8; i++)
#pragma unroll
                for (int j = 0; j < 8; j++)
                    acc[i][j] = fmaf(ar[i], br[j], acc[i][j]);
        }
        __syncthreads();
    }

    const int mbase = m0 + ty * 8;
    const int nbase = n0 + tx * 8;
    float bv[8];
#pragma unroll
    for (int j = 0; j < 8; j++) bv[j] = bias[nbase + j];
#pragma unroll
    for (int i = 0; i < 8; i++) {
        float4 v0 = make_float4(acc[i][0] + bv[0], acc[i][1] + bv[1],
                                acc[i][2] + bv[2], acc[i][3] + bv[3]);
        float4 v1 = make_float4(acc[i][4] + bv[4], acc[i][5] + bv[5],
                                acc[i][6] + bv[6], acc[i][7] + bv[7]);
        float* p = out + (size_t)(mbase + i) * CH + nbase;
        *reinterpret_cast<float4*>(p)     = v0;
        *reinterpret_cast<float4*>(p + 4) = v1;
    }
}

// ---------------------------------------------------------------------------
extern "C" void kernel_launch(void* const* d_in, const int* in_sizes, int n_in,
                              void* d_out, int out_size)
{
    const float* x      = (const float*)d_in[0];
    const float* w_attn = (const float*)d_in[1];
    const float* b_attn = (const float*)d_in[2];
    const float* w_proj = (const float*)d_in[3];
    const float* b_proj = (const float*)d_in[4];
    float* out = (float*)d_out;

    const int ATTN_SMEM = 4 * 64 * PAD * sizeof(float);  // 69632 B
    cudaFuncSetAttribute(attn_kernel,
                         cudaFuncAttributeMaxDynamicSharedMemorySize, ATTN_SMEM);

    // 1) QKV GEMM: grid (3072/128, 8192/128)
    qkv_gemm_kernel<<<dim3(24, 64), 256>>>(x, w_attn, b_attn);

    // 2) Attention: grid (32 q-tiles, B*NH)
    attn_kernel<<<dim3(32, BATCH * NHEAD), 256, ATTN_SMEM>>>();

    // 3) Projection: grid (1024/128, 8192/128)
    proj_gemm_kernel<<<dim3(8, 64), 256>>>(w_proj, b_proj, out);
}

// round 2
// speedup vs baseline: 1.6277x; 1.6277x over previous
#include <cuda_runtime.h>
#include <cstdint>

#define BATCH 4
#define SEQ   2048
#define CH    1024
#define NHEAD 16
#define HDIM  64
#define PAD   68   // attention smem row stride

// Scratch (allocation-free rule: __device__ globals)
__device__ float g_q[BATCH * NHEAD * HDIM * SEQ];   // [b,h,d,t]
__device__ float g_k[BATCH * NHEAD * HDIM * SEQ];   // [b,h,d,t]
__device__ float g_v[BATCH * NHEAD * SEQ * HDIM];   // [b,h,t,d]
__device__ float g_att[BATCH * SEQ * CH];           // [b,t,c]

__device__ __forceinline__ float to_tf32(float x) {
    float r;
    asm("cvt.rna.tf32.f32 %0, %1;" : "=f"(r) : "f"(x));
    return r;
}

#define MMA_TF32(d, a, b)                                                  \
    asm volatile(                                                          \
        "mma.sync.aligned.m16n8k8.row.col.f32.tf32.tf32.f32 "              \
        "{%0,%1,%2,%3},{%4,%5,%6,%7},{%8,%9},{%0,%1,%2,%3};"               \
        : "+f"((d)[0]), "+f"((d)[1]), "+f"((d)[2]), "+f"((d)[3])           \
        : "r"((a)[0]), "r"((a)[1]), "r"((a)[2]), "r"((a)[3]),              \
          "r"((b)[0]), "r"((b)[1]))

// ---------------------------------------------------------------------------
// TF32 GEMM core: block 128(M)x128(N), BK=32, 8 warps as 2(M)x4(N),
// warp tile 64x32 (4 m16-tiles x 4 n8-tiles).
// As: [128][36] row-major (stride 36 => frag banks 4r+c, conflict-free)
// Bs: [32][136] k-major    (stride 136 => frag banks 8c+r, conflict-free)
// ---------------------------------------------------------------------------
#define AS_STRIDE 36
#define BS_STRIDE 136

// Accumulate the 128x128 tile. Returns acc in-place.
__device__ __forceinline__ void tf32_gemm_tile(
    const float* __restrict__ X, int ldx,
    const float* __restrict__ W, int ldw,
    int m0, int n0, int Ktot,
    float acc[4][4][4],
    float* As, float* Bs,
    int tid)
{
    const int lane = tid & 31;
    const int wid  = tid >> 5;
    const int wm   = wid & 1;   // 0..1
    const int wn   = wid >> 1;  // 0..3
    const int lr   = lane >> 2; // 0..7
    const int lc   = lane & 3;  // 0..3

    for (int k0 = 0; k0 < Ktot; k0 += 32) {
        // Load A tile 128x32 (coalesced 32B per 8 lanes), cvt to tf32
#pragma unroll
        for (int it = 0; it < 4; it++) {
            int idx = it * 256 + tid;
            int m = idx >> 3;
            int kg = idx & 7;
            float4 v = *reinterpret_cast<const float4*>(
                X + (size_t)(m0 + m) * ldx + k0 + kg * 4);
            v.x = to_tf32(v.x); v.y = to_tf32(v.y);
            v.z = to_tf32(v.z); v.w = to_tf32(v.w);
            *reinterpret_cast<float4*>(&As[m * AS_STRIDE + kg * 4]) = v;
        }
        // Load B tile 32x128 (fully coalesced rows), cvt to tf32
#pragma unroll
        for (int it = 0; it < 4; it++) {
            int idx = it * 256 + tid;
            int k = idx >> 5;
            int n4 = idx & 31;
            float4 v = *reinterpret_cast<const float4*>(
                W + (size_t)(k0 + k) * ldw + n0 + n4 * 4);
            v.x = to_tf32(v.x); v.y = to_tf32(v.y);
            v.z = to_tf32(v.z); v.w = to_tf32(v.w);
            *reinterpret_cast<float4*>(&Bs[k * BS_STRIDE + n4 * 4]) = v;
        }
        __syncthreads();

#pragma unroll
        for (int kq = 0; kq < 4; kq++) {
            const int kk = kq * 8;
            uint32_t a[4][4], b[4][2];
#pragma unroll
            for (int mt = 0; mt < 4; mt++) {
                int base = (wm * 64 + mt * 16 + lr) * AS_STRIDE + kk + lc;
                a[mt][0] = __float_as_uint(As[base]);
                a[mt][1] = __float_as_uint(As[base + 8 * AS_STRIDE]);
                a[mt][2] = __float_as_uint(As[base + 4]);
                a[mt][3] = __float_as_uint(As[base + 8 * AS_STRIDE + 4]);
            }
#pragma unroll
            for (int nt = 0; nt < 4; nt++) {
                int bcol = wn * 32 + nt * 8 + lr;
                b[nt][0] = __float_as_uint(Bs[(kk + lc) * BS_STRIDE + bcol]);
                b[nt][1] = __float_as_uint(Bs[(kk + 4 + lc) * BS_STRIDE + bcol]);
            }
#pragma unroll
            for (int mt = 0; mt < 4; mt++)
#pragma unroll
                for (int nt = 0; nt < 4; nt++)
                    MMA_TF32(acc[mt][nt], a[mt], b[nt]);
        }
        __syncthreads();
    }
}

// ---------------------------------------------------------------------------
// Kernel 1: QKV GEMM with scatter epilogue into g_q/g_k ([b,h,d,t]) and
// g_v ([b,h,t,d]).
// ---------------------------------------------------------------------------
__global__ __launch_bounds__(256) void qkv_gemm_kernel(
    const float* __restrict__ X, const float* __restrict__ W,
    const float* __restrict__ bias)
{
    __shared__ float As[128 * AS_STRIDE];
    __shared__ float Bs[32 * BS_STRIDE];
    const int tid = threadIdx.x;
    const int m0 = blockIdx.y * 128;
    const int n0 = blockIdx.x * 128;

    float acc[4][4][4];
#pragma unroll
    for (int i = 0; i < 4; i++)
#pragma unroll
        for (int j = 0; j < 4; j++)
#pragma unroll
            for (int q = 0; q < 4; q++) acc[i][j][q] = 0.f;

    tf32_gemm_tile(X, CH, W, 3 * CH, m0, n0, CH, acc, As, Bs, tid);

    const int lane = tid & 31;
    const int wid  = tid >> 5;
    const int wm   = wid & 1;
    const int wn   = wid >> 1;
    const int lr   = lane >> 2;
    const int lc   = lane & 3;

    const int sec = n0 >> 10;  // block never straddles q/k/v sections

#pragma unroll
    for (int mt = 0; mt < 4; mt++) {
        int r0 = m0 + wm * 64 + mt * 16 + lr;
#pragma unroll
        for (int nt = 0; nt < 4; nt++) {
            int c0 = n0 + wn * 32 + nt * 8 + lc * 2;
            float b0 = bias[c0], b1 = bias[c0 + 1];
            float v00 = acc[mt][nt][0] + b0, v01 = acc[mt][nt][1] + b1;
            float v10 = acc[mt][nt][2] + b0, v11 = acc[mt][nt][3] + b1;

            int bb = r0 >> 11;
            int t  = r0 & (SEQ - 1);
            int n1 = c0 & (CH - 1);
            int h  = n1 >> 6;
            int d  = n1 & 63;

            if (sec < 2) {
                float* dst = (sec == 0) ? g_q : g_k;
                size_t base = ((size_t)(bb * NHEAD + h) * HDIM + d) * SEQ;
                dst[base + t]            = v00;
                dst[base + SEQ + t]      = v01;   // d+1
                dst[base + t + 8]        = v10;   // row r0+8
                dst[base + SEQ + t + 8]  = v11;
            } else {
                size_t base = ((size_t)(bb * NHEAD + h) * SEQ + t) * HDIM + d;
                *reinterpret_cast<float2*>(&g_v[base]) = make_float2(v00, v01);
                *reinterpret_cast<float2*>(&g_v[base + 8 * HDIM]) =
                    make_float2(v10, v11);
            }
        }
    }
}

// ---------------------------------------------------------------------------
// Kernel 3: output projection (same core, row-major epilogue)
// ---------------------------------------------------------------------------
__global__ __launch_bounds__(256) void proj_gemm_kernel(
    const float* __restrict__ W, const float* __restrict__ bias,
    float* __restrict__ out)
{
    __shared__ float As[128 * AS_STRIDE];
    __shared__ float Bs[32 * BS_STRIDE];
    const int tid = threadIdx.x;
    const int m0 = blockIdx.y * 128;
    const int n0 = blockIdx.x * 128;

    float acc[4][4][4];
#pragma unroll
    for (int i = 0; i < 4; i++)
#pragma unroll
        for (int j = 0; j < 4; j++)
#pragma unroll
            for (int q = 0; q < 4; q++) acc[i][j][q] = 0.f;

    tf32_gemm_tile(g_att, CH, W, CH, m0, n0, CH, acc, As, Bs, tid);

    const int lane = tid & 31;
    const int wid  = tid >> 5;
    const int wm   = wid & 1;
    const int wn   = wid >> 1;
    const int lr   = lane >> 2;
    const int lc   = lane & 3;

#pragma unroll
    for (int mt = 0; mt < 4; mt++) {
        int r0 = m0 + wm * 64 + mt * 16 + lr;
#pragma unroll
        for (int nt = 0; nt < 4; nt++) {
            int c0 = n0 + wn * 32 + nt * 8 + lc * 2;
            float b0 = bias[c0], b1 = bias[c0 + 1];
            *reinterpret_cast<float2*>(&out[(size_t)r0 * CH + c0]) =
                make_float2(acc[mt][nt][0] + b0, acc[mt][nt][1] + b1);
            *reinterpret_cast<float2*>(&out[(size_t)(r0 + 8) * CH + c0]) =
                make_float2(acc[mt][nt][2] + b0, acc[mt][nt][3] + b1);
        }
    }
}

// ---------------------------------------------------------------------------
// Kernel 2: causal flash attention, fp32 (unchanged from round 1 — proven).
// ---------------------------------------------------------------------------
__global__ __launch_bounds__(256) void attn_kernel()
{
    extern __shared__ float sm[];
    float* Qs = sm;                    // [64][PAD]  (d-major)
    float* Ks = sm + 64 * PAD;         // [64][PAD]  (d-major)
    float* Vs = sm + 2 * 64 * PAD;     // [64][PAD]  (kv-major)
    float* Pt = sm + 3 * 64 * PAD;     // [64][PAD]  P^T: [kv][q]

    const int tid = threadIdx.x;
    const int tx = tid & 15;
    const int ty = tid >> 4;
    const int qt = (int)gridDim.x - 1 - (int)blockIdx.x;  // big tiles first
    const int bh = blockIdx.y;
    const int q0 = qt * 64;

    const float* qp = g_q + (size_t)bh * HDIM * SEQ;
    const float* kp = g_k + (size_t)bh * HDIM * SEQ;
    const float* vp = g_v + (size_t)bh * SEQ * HDIM;

#pragma unroll
    for (int it = 0; it < 4; it++) {
        int idx = it * 256 + tid;
        int d = idx >> 4;
        int rg = (idx & 15) * 4;
        float4 v = *reinterpret_cast<const float4*>(qp + (size_t)d * SEQ + q0 + rg);
        v.x *= 0.125f; v.y *= 0.125f; v.z *= 0.125f; v.w *= 0.125f;
        *reinterpret_cast<float4*>(&Qs[d * PAD + rg]) = v;
    }

    float m_i[4] = {-1e30f, -1e30f, -1e30f, -1e30f};
    float l_i[4] = {0.f, 0.f, 0.f, 0.f};
    float o[4][4] = {};

    for (int kt = 0; kt <= qt; kt++) {
        const int k0 = kt * 64;
        __syncthreads();
#pragma unroll
        for (int it = 0; it < 4; it++) {
            int idx = it * 256 + tid;
            int d = idx >> 4;
            int rg = (idx & 15) * 4;
            *reinterpret_cast<float4*>(&Ks[d * PAD + rg]) =
                *reinterpret_cast<const float4*>(kp + (size_t)d * SEQ + k0 + rg);
            *reinterpret_cast<float4*>(&Vs[d * PAD + rg]) =
                *reinterpret_cast<const float4*>(vp + (size_t)(k0 + d) * HDIM + rg);
        }
        __syncthreads();

        float s[4][4] = {};
#pragma unroll 8
        for (int d = 0; d < 64; d++) {
            float qa[4], ka[4];
            *reinterpret_cast<float4*>(qa) = *reinterpret_cast<float4*>(&Qs[d * PAD + ty * 4]);
            *reinterpret_cast<float4*>(ka) = *reinterpret_cast<float4*>(&Ks[d * PAD + tx * 4]);
#pragma unroll
            for (int i = 0; i < 4; i++)
#pragma unroll
                for (int j = 0; j < 4; j++)
                    s[i][j] = fmaf(qa[i], ka[j], s[i][j]);
        }

        if (kt == qt) {
#pragma unroll
            for (int i = 0; i < 4; i++)
#pragma unroll
                for (int j = 0; j < 4; j++)
                    if (tx * 4 + j > ty * 4 + i) s[i][j] = -1e30f;
        }

#pragma unroll
        for (int i = 0; i < 4; i++) {
            float rm = fmaxf(fmaxf(s[i][0], s[i][1]), fmaxf(s[i][2], s[i][3]));
#pragma unroll
            for (int w = 8; w >= 1; w >>= 1)
                rm = fmaxf(rm, __shfl_xor_sync(0xffffffffu, rm, w));
            float mn = fmaxf(m_i[i], rm);
            float corr = __expf(m_i[i] - mn);
            m_i[i] = mn;
            float rs = 0.f;
#pragma unroll
            for (int j = 0; j < 4; j++) {
                s[i][j] = __expf(s[i][j] - mn);
                rs += s[i][j];
            }
#pragma unroll
            for (int w = 8; w >= 1; w >>= 1)
                rs += __shfl_xor_sync(0xffffffffu, rs, w);
            l_i[i] = l_i[i] * corr + rs;
#pragma unroll
            for (int j = 0; j < 4; j++) o[i][j] *= corr;
        }

#pragma unroll
        for (int j = 0; j < 4; j++)
#pragma unroll
            for (int i = 0; i < 4; i++)
                Pt[(tx * 4 + j) * PAD + ty * 4 + i] = s[i][j];
        __syncthreads();

#pragma unroll 8
        for (int kk = 0; kk < 64; kk++) {
            float pa[4], va[4];
            *reinterpret_cast<float4*>(pa) = *reinterpret_cast<float4*>(&Pt[kk * PAD + ty * 4]);
            *reinterpret_cast<float4*>(va) = *reinterpret_cast<float4*>(&Vs[kk * PAD + tx * 4]);
#pragma unroll
            for (int i = 0; i < 4; i++)
#pragma unroll
                for (int j = 0; j < 4; j++)
                    o[i][j] = fmaf(pa[i], va[j], o[i][j]);
        }
    }

    const int b = bh >> 4, h = bh & 15;
#pragma unroll
    for (int i = 0; i < 4; i++) {
        float inv = 1.0f / l_i[i];
        float4 ov = make_float4(o[i][0] * inv, o[i][1] * inv,
                                o[i][2] * inv, o[i][3] * inv);
        *reinterpret_cast<float4*>(
            &g_att[(size_t)(b * SEQ + q0 + ty * 4 + i) * CH + h * 64 + tx * 4]) = ov;
    }
}

// ---------------------------------------------------------------------------
extern "C" void kernel_launch(void* const* d_in, const int* in_sizes, int n_in,
                              void* d_out, int out_size)
{
    const float* x      = (const float*)d_in[0];
    const float* w_attn = (const float*)d_in[1];
    const float* b_attn = (const float*)d_in[2];
    const float* w_proj = (const float*)d_in[3];
    const float* b_proj = (const float*)d_in[4];
    float* out = (float*)d_out;

    const int ATTN_SMEM = 4 * 64 * PAD * sizeof(float);  // 69632 B
    cudaFuncSetAttribute(attn_kernel,
                         cudaFuncAttributeMaxDynamicSharedMemorySize, ATTN_SMEM);

    // 1) QKV GEMM: grid (3072/128, 8192/128)
    qkv_gemm_kernel<<<dim3(24, 64), 256>>>(x, w_attn, b_attn);

    // 2) Attention: grid (32 q-tiles, B*NH)
    attn_kernel<<<dim3(32, BATCH * NHEAD), 256, ATTN_SMEM>>>();

    // 3) Projection: grid (1024/128, 8192/128)
    proj_gemm_kernel<<<dim3(8, 64), 256>>>(w_proj, b_proj, out);
}

// round 3
// speedup vs baseline: 2.9039x; 1.7840x over previous
#include <cuda_runtime.h>
#include <cstdint>

#define BATCH 4
#define SEQ   2048
#define CH    1024
#define NHEAD 16
#define HDIM  64

// Scratch (allocation-free rule: __device__ globals). All [b,h,t,d].
__device__ float g_q[BATCH * NHEAD * SEQ * HDIM];
__device__ float g_k[BATCH * NHEAD * SEQ * HDIM];
__device__ float g_v[BATCH * NHEAD * SEQ * HDIM];
__device__ float g_att[BATCH * SEQ * CH];           // [b,t,c]

__device__ __forceinline__ float to_tf32(float x) {
    float r;
    asm("cvt.rna.tf32.f32 %0, %1;" : "=f"(r) : "f"(x));
    return r;
}

#define MMA_TF32(d, a, b)                                                  \
    asm volatile(                                                          \
        "mma.sync.aligned.m16n8k8.row.col.f32.tf32.tf32.f32 "              \
        "{%0,%1,%2,%3},{%4,%5,%6,%7},{%8,%9},{%0,%1,%2,%3};"               \
        : "+f"((d)[0]), "+f"((d)[1]), "+f"((d)[2]), "+f"((d)[3])           \
        : "r"((a)[0]), "r"((a)[1]), "r"((a)[2]), "r"((a)[3]),              \
          "r"((b)[0]), "r"((b)[1]))

// ---------------------------------------------------------------------------
// TF32 GEMM core (unchanged from round 2): 128x128 tile, BK=32, 8 warps 2x4.
// ---------------------------------------------------------------------------
#define AS_STRIDE 36
#define BS_STRIDE 136

__device__ __forceinline__ void tf32_gemm_tile(
    const float* __restrict__ X, int ldx,
    const float* __restrict__ W, int ldw,
    int m0, int n0, int Ktot,
    float acc[4][4][4],
    float* As, float* Bs,
    int tid)
{
    const int lane = tid & 31;
    const int wid  = tid >> 5;
    const int wm   = wid & 1;
    const int wn   = wid >> 1;
    const int lr   = lane >> 2;
    const int lc   = lane & 3;

    for (int k0 = 0; k0 < Ktot; k0 += 32) {
#pragma unroll
        for (int it = 0; it < 4; it++) {
            int idx = it * 256 + tid;
            int m = idx >> 3;
            int kg = idx & 7;
            float4 v = *reinterpret_cast<const float4*>(
                X + (size_t)(m0 + m) * ldx + k0 + kg * 4);
            v.x = to_tf32(v.x); v.y = to_tf32(v.y);
            v.z = to_tf32(v.z); v.w = to_tf32(v.w);
            *reinterpret_cast<float4*>(&As[m * AS_STRIDE + kg * 4]) = v;
        }
#pragma unroll
        for (int it = 0; it < 4; it++) {
            int idx = it * 256 + tid;
            int k = idx >> 5;
            int n4 = idx & 31;
            float4 v = *reinterpret_cast<const float4*>(
                W + (size_t)(k0 + k) * ldw + n0 + n4 * 4);
            v.x = to_tf32(v.x); v.y = to_tf32(v.y);
            v.z = to_tf32(v.z); v.w = to_tf32(v.w);
            *reinterpret_cast<float4*>(&Bs[k * BS_STRIDE + n4 * 4]) = v;
        }
        __syncthreads();

#pragma unroll
        for (int kq = 0; kq < 4; kq++) {
            const int kk = kq * 8;
            uint32_t a[4][4], b[4][2];
#pragma unroll
            for (int mt = 0; mt < 4; mt++) {
                int base = (wm * 64 + mt * 16 + lr) * AS_STRIDE + kk + lc;
                a[mt][0] = __float_as_uint(As[base]);
                a[mt][1] = __float_as_uint(As[base + 8 * AS_STRIDE]);
                a[mt][2] = __float_as_uint(As[base + 4]);
                a[mt][3] = __float_as_uint(As[base + 8 * AS_STRIDE + 4]);
            }
#pragma unroll
            for (int nt = 0; nt < 4; nt++) {
                int bcol = wn * 32 + nt * 8 + lr;
                b[nt][0] = __float_as_uint(Bs[(kk + lc) * BS_STRIDE + bcol]);
                b[nt][1] = __float_as_uint(Bs[(kk + 4 + lc) * BS_STRIDE + bcol]);
            }
#pragma unroll
            for (int mt = 0; mt < 4; mt++)
#pragma unroll
                for (int nt = 0; nt < 4; nt++)
                    MMA_TF32(acc[mt][nt], a[mt], b[nt]);
        }
        __syncthreads();
    }
}

// ---------------------------------------------------------------------------
// Kernel 1: QKV GEMM; epilogue writes q,k,v uniformly as [b,h,t,d].
// Softmax scale (1/8) folded into q.
// ---------------------------------------------------------------------------
__global__ __launch_bounds__(256) void qkv_gemm_kernel(
    const float* __restrict__ X, const float* __restrict__ W,
    const float* __restrict__ bias)
{
    __shared__ float As[128 * AS_STRIDE];
    __shared__ float Bs[32 * BS_STRIDE];
    const int tid = threadIdx.x;
    const int m0 = blockIdx.y * 128;
    const int n0 = blockIdx.x * 128;

    float acc[4][4][4];
#pragma unroll
    for (int i = 0; i < 4; i++)
#pragma unroll
        for (int j = 0; j < 4; j++)
#pragma unroll
            for (int q = 0; q < 4; q++) acc[i][j][q] = 0.f;

    tf32_gemm_tile(X, CH, W, 3 * CH, m0, n0, CH, acc, As, Bs, tid);

    const int lane = tid & 31;
    const int wid  = tid >> 5;
    const int wm   = wid & 1;
    const int wn   = wid >> 1;
    const int lr   = lane >> 2;
    const int lc   = lane & 3;

    const int sec = n0 >> 10;  // 0=q 1=k 2=v (tile never straddles)
    float* dst = (sec == 0) ? g_q : (sec == 1 ? g_k : g_v);
    const float scale = (sec == 0) ? 0.125f : 1.0f;

#pragma unroll
    for (int mt = 0; mt < 4; mt++) {
        int r0 = m0 + wm * 64 + mt * 16 + lr;
        int bb = r0 >> 11;
        int t  = r0 & (SEQ - 1);
#pragma unroll
        for (int nt = 0; nt < 4; nt++) {
            int c0 = n0 + wn * 32 + nt * 8 + lc * 2;
            float b0 = bias[c0], b1 = bias[c0 + 1];
            int n1 = c0 & (CH - 1);
            int h  = n1 >> 6;
            int d  = n1 & 63;
            size_t base = ((size_t)((bb * NHEAD + h) * SEQ + t)) * HDIM + d;
            *reinterpret_cast<float2*>(&dst[base]) =
                make_float2((acc[mt][nt][0] + b0) * scale,
                            (acc[mt][nt][1] + b1) * scale);
            *reinterpret_cast<float2*>(&dst[base + 8 * HDIM]) =
                make_float2((acc[mt][nt][2] + b0) * scale,
                            (acc[mt][nt][3] + b1) * scale);
        }
    }
}

// ---------------------------------------------------------------------------
// Kernel 3: output projection (unchanged)
// ---------------------------------------------------------------------------
__global__ __launch_bounds__(256) void proj_gemm_kernel(
    const float* __restrict__ W, const float* __restrict__ bias,
    float* __restrict__ out)
{
    __shared__ float As[128 * AS_STRIDE];
    __shared__ float Bs[32 * BS_STRIDE];
    const int tid = threadIdx.x;
    const int m0 = blockIdx.y * 128;
    const int n0 = blockIdx.x * 128;

    float acc[4][4][4];
#pragma unroll
    for (int i = 0; i < 4; i++)
#pragma unroll
        for (int j = 0; j < 4; j++)
#pragma unroll
            for (int q = 0; q < 4; q++) acc[i][j][q] = 0.f;

    tf32_gemm_tile(g_att, CH, W, CH, m0, n0, CH, acc, As, Bs, tid);

    const int lane = tid & 31;
    const int wid  = tid >> 5;
    const int wm   = wid & 1;
    const int wn   = wid >> 1;
    const int lr   = lane >> 2;
    const int lc   = lane & 3;

#pragma unroll
    for (int mt = 0; mt < 4; mt++) {
        int r0 = m0 + wm * 64 + mt * 16 + lr;
#pragma unroll
        for (int nt = 0; nt < 4; nt++) {
            int c0 = n0 + wn * 32 + nt * 8 + lc * 2;
            float b0 = bias[c0], b1 = bias[c0 + 1];
            *reinterpret_cast<float2*>(&out[(size_t)r0 * CH + c0]) =
                make_float2(acc[mt][nt][0] + b0, acc[mt][nt][1] + b1);
            *reinterpret_cast<float2*>(&out[(size_t)(r0 + 8) * CH + c0]) =
                make_float2(acc[mt][nt][2] + b0, acc[mt][nt][3] + b1);
        }
    }
}

// ---------------------------------------------------------------------------
// Kernel 2: causal flash attention with TF32 tensor cores.
// Block: 128 q-rows x 64 kv per iter; 8 warps, 16 q-rows each.
// Q fragments in registers; K/V staged in smem; P via per-warp smem slab
// aliased onto the (dead after frag-load) Q smem region.
// ---------------------------------------------------------------------------
#define QS_STRIDE 68   // bank pattern (4*lr+lc): conflict-free for A/B-row frags
#define VS_STRIDE 72   // bank pattern (8*lc+lr): conflict-free for V B-frags

__global__ __launch_bounds__(256) void attn_kernel()
{
    extern __shared__ float sm[];
    float* Qs = sm;                          // [128][68]; later Pt (per warp)
    float* Ks = sm + 128 * QS_STRIDE;        // [64][68]
    float* Vs = Ks + 64 * QS_STRIDE;         // [64][72]

    const int tid  = threadIdx.x;
    const int lane = tid & 31;
    const int wq   = tid >> 5;      // warp -> 16-row q slab
    const int lr   = lane >> 2;
    const int lc   = lane & 3;

    const int qt = (int)gridDim.x - 1 - (int)blockIdx.x;  // big tiles first
    const int bh = blockIdx.y;
    const int q0 = qt * 128;

    const float* qp = g_q + (size_t)bh * SEQ * HDIM;
    const float* kp = g_k + (size_t)bh * SEQ * HDIM;
    const float* vp = g_v + (size_t)bh * SEQ * HDIM;

    // Stage Q tile (128x64) into smem
#pragma unroll
    for (int it = 0; it < 8; it++) {
        int idx = it * 256 + tid;
        int row = idx >> 4;
        int c4  = (idx & 15) * 4;
        *reinterpret_cast<float4*>(&Qs[row * QS_STRIDE + c4]) =
            *reinterpret_cast<const float4*>(qp + (size_t)(q0 + row) * HDIM + c4);
    }
    __syncthreads();

    // Q fragments -> registers (tf32-rounded). 8 k-steps of 8.
    uint32_t qf[8][4];
    {
        int rbase = (wq * 16 + lr) * QS_STRIDE;
#pragma unroll
        for (int s = 0; s < 8; s++) {
            qf[s][0] = __float_as_uint(to_tf32(Qs[rbase + s * 8 + lc]));
            qf[s][1] = __float_as_uint(to_tf32(Qs[rbase + 8 * QS_STRIDE + s * 8 + lc]));
            qf[s][2] = __float_as_uint(to_tf32(Qs[rbase + s * 8 + 4 + lc]));
            qf[s][3] = __float_as_uint(to_tf32(Qs[rbase + 8 * QS_STRIDE + s * 8 + 4 + lc]));
        }
    }

    float* Pt = Qs + wq * 16 * QS_STRIDE;   // per-warp 16x64 slab (own rows)

    float o[8][4] = {};
    float m0v = -1e30f, m1v = -1e30f;
    float l0v = 0.f, l1v = 0.f;

    const int nkt  = 2 * qt + 2;
    const int r_hi = q0 + wq * 16 + 15;     // top q row of this warp

    for (int kt = 0; kt < nkt; kt++) {
        const int k0 = kt * 64;
        __syncthreads();   // prior-iter Ks/Vs readers done
#pragma unroll
        for (int it = 0; it < 4; it++) {
            int idx = it * 256 + tid;
            int row = idx >> 4;
            int c4  = (idx & 15) * 4;
            float4 kv4 = *reinterpret_cast<const float4*>(
                kp + (size_t)(k0 + row) * HDIM + c4);
            kv4.x = to_tf32(kv4.x); kv4.y = to_tf32(kv4.y);
            kv4.z = to_tf32(kv4.z); kv4.w = to_tf32(kv4.w);
            *reinterpret_cast<float4*>(&Ks[row * QS_STRIDE + c4]) = kv4;
            float4 vv4 = *reinterpret_cast<const float4*>(
                vp + (size_t)(k0 + row) * HDIM + c4);
            vv4.x = to_tf32(vv4.x); vv4.y = to_tf32(vv4.y);
            vv4.z = to_tf32(vv4.z); vv4.w = to_tf32(vv4.w);
            *reinterpret_cast<float4*>(&Vs[row * VS_STRIDE + c4]) = vv4;
        }
        __syncthreads();

        if (k0 > r_hi) continue;   // whole warp tile masked (warp-uniform)

        // ---- S = Q @ K^T : per-warp 16x64, 64 mmas ----
        float sacc[8][4];
#pragma unroll
        for (int nt = 0; nt < 8; nt++)
#pragma unroll
            for (int q = 0; q < 4; q++) sacc[nt][q] = 0.f;

#pragma unroll
        for (int s = 0; s < 8; s++) {
#pragma unroll
            for (int nt = 0; nt < 8; nt++) {
                uint32_t b[2];
                b[0] = __float_as_uint(Ks[(nt * 8 + lr) * QS_STRIDE + s * 8 + lc]);
                b[1] = __float_as_uint(Ks[(nt * 8 + lr) * QS_STRIDE + s * 8 + 4 + lc]);
                MMA_TF32(sacc[nt], qf[s], b);
            }
        }

        // ---- causal mask (only the last two kv tiles of each q block) ----
        if (kt >= 2 * qt) {
            int r0g = q0 + wq * 16 + lr;
#pragma unroll
            for (int nt = 0; nt < 8; nt++) {
                int c0g = k0 + nt * 8 + 2 * lc;
                if (c0g     > r0g)     sacc[nt][0] = -1e30f;
                if (c0g + 1 > r0g)     sacc[nt][1] = -1e30f;
                if (c0g     > r0g + 8) sacc[nt][2] = -1e30f;
                if (c0g + 1 > r0g + 8) sacc[nt][3] = -1e30f;
            }
        }

        // ---- online softmax (rows lr and lr+8; quad = 4 lanes/row) ----
        float rm0 = -1e30f, rm1 = -1e30f;
#pragma unroll
        for (int nt = 0; nt < 8; nt++) {
            rm0 = fmaxf(rm0, fmaxf(sacc[nt][0], sacc[nt][1]));
            rm1 = fmaxf(rm1, fmaxf(sacc[nt][2], sacc[nt][3]));
        }
        rm0 = fmaxf(rm0, __shfl_xor_sync(0xffffffffu, rm0, 1));
        rm0 = fmaxf(rm0, __shfl_xor_sync(0xffffffffu, rm0, 2));
        rm1 = fmaxf(rm1, __shfl_xor_sync(0xffffffffu, rm1, 1));
        rm1 = fmaxf(rm1, __shfl_xor_sync(0xffffffffu, rm1, 2));

        float mn0 = fmaxf(m0v, rm0);
        float mn1 = fmaxf(m1v, rm1);
        float cr0 = __expf(m0v - mn0);
        float cr1 = __expf(m1v - mn1);
        m0v = mn0; m1v = mn1;

        float rs0 = 0.f, rs1 = 0.f;
#pragma unroll
        for (int nt = 0; nt < 8; nt++) {
            sacc[nt][0] = __expf(sacc[nt][0] - mn0);
            sacc[nt][1] = __expf(sacc[nt][1] - mn0);
            sacc[nt][2] = __expf(sacc[nt][2] - mn1);
            sacc[nt][3] = __expf(sacc[nt][3] - mn1);
            rs0 += sacc[nt][0] + sacc[nt][1];
            rs1 += sacc[nt][2] + sacc[nt][3];
        }
        rs0 += __shfl_xor_sync(0xffffffffu, rs0, 1);
        rs0 += __shfl_xor_sync(0xffffffffu, rs0, 2);
        rs1 += __shfl_xor_sync(0xffffffffu, rs1, 1);
        rs1 += __shfl_xor_sync(0xffffffffu, rs1, 2);
        l0v = l0v * cr0 + rs0;
        l1v = l1v * cr1 + rs1;
#pragma unroll
        for (int nt = 0; nt < 8; nt++) {
            o[nt][0] *= cr0; o[nt][1] *= cr0;
            o[nt][2] *= cr1; o[nt][3] *= cr1;
        }

        // ---- P -> per-warp smem slab (tf32-rounded) ----
#pragma unroll
        for (int nt = 0; nt < 8; nt++) {
            *reinterpret_cast<float2*>(&Pt[lr * QS_STRIDE + nt * 8 + 2 * lc]) =
                make_float2(to_tf32(sacc[nt][0]), to_tf32(sacc[nt][1]));
            *reinterpret_cast<float2*>(&Pt[(lr + 8) * QS_STRIDE + nt * 8 + 2 * lc]) =
                make_float2(to_tf32(sacc[nt][2]), to_tf32(sacc[nt][3]));
        }
        __syncwarp();

        // ---- O += P @ V : 64 mmas ----
#pragma unroll
        for (int s = 0; s < 8; s++) {
            uint32_t a[4];
            a[0] = __float_as_uint(Pt[lr * QS_STRIDE + s * 8 + lc]);
            a[1] = __float_as_uint(Pt[(lr + 8) * QS_STRIDE + s * 8 + lc]);
            a[2] = __float_as_uint(Pt[lr * QS_STRIDE + s * 8 + 4 + lc]);
            a[3] = __float_as_uint(Pt[(lr + 8) * QS_STRIDE + s * 8 + 4 + lc]);
#pragma unroll
            for (int nt = 0; nt < 8; nt++) {
                uint32_t b[2];
                b[0] = __float_as_uint(Vs[(s * 8 + lc) * VS_STRIDE + nt * 8 + lr]);
                b[1] = __float_as_uint(Vs[(s * 8 + 4 + lc) * VS_STRIDE + nt * 8 + lr]);
                MMA_TF32(o[nt], a, b);
            }
        }
        __syncwarp();  // keep Pt reads ahead of next-iter writes within warp order
    }

    // ---- normalize + store to [b,t,c] ----
    const int b = bh >> 4, h = bh & 15;
    const int r0g = q0 + wq * 16 + lr;
    const float inv0 = 1.0f / l0v;
    const float inv1 = 1.0f / l1v;
#pragma unroll
    for (int nt = 0; nt < 8; nt++) {
        int cg = h * 64 + nt * 8 + 2 * lc;
        *reinterpret_cast<float2*>(&g_att[(size_t)(b * SEQ + r0g) * CH + cg]) =
            make_float2(o[nt][0] * inv0, o[nt][1] * inv0);
        *reinterpret_cast<float2*>(&g_att[(size_t)(b * SEQ + r0g + 8) * CH + cg]) =
            make_float2(o[nt][2] * inv1, o[nt][3] * inv1);
    }
}

// ---------------------------------------------------------------------------
extern "C" void kernel_launch(void* const* d_in, const int* in_sizes, int n_in,
                              void* d_out, int out_size)
{
    const float* x      = (const float*)d_in[0];
    const float* w_attn = (const float*)d_in[1];
    const float* b_attn = (const float*)d_in[2];
    const float* w_proj = (const float*)d_in[3];
    const float* b_proj = (const float*)d_in[4];
    float* out = (float*)d_out;

    const int ATTN_SMEM =
        (128 * QS_STRIDE + 64 * QS_STRIDE + 64 * VS_STRIDE) * (int)sizeof(float);
    cudaFuncSetAttribute(attn_kernel,
                         cudaFuncAttributeMaxDynamicSharedMemorySize, ATTN_SMEM);

    // 1) QKV GEMM: grid (3072/128, 8192/128)
    qkv_gemm_kernel<<<dim3(24, 64), 256>>>(x, w_attn, b_attn);

    // 2) Attention: grid (16 q-tiles, B*NH)
    attn_kernel<<<dim3(16, BATCH * NHEAD), 256, ATTN_SMEM>>>();

    // 3) Projection: grid (1024/128, 8192/128)
    proj_gemm_kernel<<<dim3(8, 64), 256>>>(w_proj, b_proj, out);
}

// round 4
// speedup vs baseline: 3.3534x; 1.1548x over previous
#include <cuda_runtime.h>
#include <cstdint>

#define BATCH 4
#define SEQ   2048
#define CH    1024
#define NHEAD 16
#define HDIM  64

// Scratch (allocation-free rule: __device__ globals). q/k/v are [b,h,t,d].
__device__ float g_q[BATCH * NHEAD * SEQ * HDIM];
__device__ float g_k[BATCH * NHEAD * SEQ * HDIM];
__device__ float g_v[BATCH * NHEAD * SEQ * HDIM];
__device__ float g_att[BATCH * SEQ * CH];        // [b,t,c], tf32-rounded
__device__ float g_x [BATCH * SEQ * CH];         // x, tf32-rounded
__device__ float g_wa[CH * 3 * CH];              // w_attn, tf32-rounded
__device__ float g_wp[CH * CH];                  // w_proj, tf32-rounded

__device__ __forceinline__ float to_tf32(float x) {
    float r;
    asm("cvt.rna.tf32.f32 %0, %1;" : "=f"(r) : "f"(x));
    return r;
}

#define MMA_TF32(d, a, b)                                                  \
    asm volatile(                                                          \
        "mma.sync.aligned.m16n8k8.row.col.f32.tf32.tf32.f32 "              \
        "{%0,%1,%2,%3},{%4,%5,%6,%7},{%8,%9},{%0,%1,%2,%3};"               \
        : "+f"((d)[0]), "+f"((d)[1]), "+f"((d)[2]), "+f"((d)[3])           \
        : "r"((a)[0]), "r"((a)[1]), "r"((a)[2]), "r"((a)[3]),              \
          "r"((b)[0]), "r"((b)[1]))

#define CP_ASYNC16(dst_u32, src_ptr)                                       \
    asm volatile("cp.async.cg.shared.global [%0], [%1], 16;"               \
                 :: "r"(dst_u32), "l"(src_ptr))
#define CP_COMMIT() asm volatile("cp.async.commit_group;")
#define CP_WAIT(N)  asm volatile("cp.async.wait_group %0;" :: "n"(N))

__device__ __forceinline__ uint32_t smem_u32(const void* p) {
    return (uint32_t)__cvta_generic_to_shared(p);
}

// ---------------------------------------------------------------------------
// Convert kernel: tf32-round a float buffer into a __device__ global.
// sel: 0 -> g_x, 1 -> g_wa, 2 -> g_wp
// ---------------------------------------------------------------------------
__global__ void cvt_tf32_kernel(const float* __restrict__ src, int sel, int n4)
{
    float* dst = (sel == 0) ? g_x : (sel == 1) ? g_wa : g_wp;
    int i = blockIdx.x * blockDim.x + threadIdx.x;
    if (i < n4) {
        float4 v = reinterpret_cast<const float4*>(src)[i];
        v.x = to_tf32(v.x); v.y = to_tf32(v.y);
        v.z = to_tf32(v.z); v.w = to_tf32(v.w);
        reinterpret_cast<float4*>(dst)[i] = v;
    }
}

// ---------------------------------------------------------------------------
// TF32 GEMM core with cp.async double-buffered pipeline.
// Block 128x128, BK=32, 8 warps (2x4), warp tile 64x32.
// As buf: [128][36], Bs buf: [32][136]; 2 buffers each.
// ---------------------------------------------------------------------------
#define AS_STRIDE 36
#define BS_STRIDE 136
#define AS_BUF (128 * AS_STRIDE)
#define BS_BUF (32 * BS_STRIDE)
#define GEMM_SMEM ((2 * AS_BUF + 2 * BS_BUF) * (int)sizeof(float))

__device__ __forceinline__ void gemm_issue_loads(
    const float* __restrict__ X, int ldx,
    const float* __restrict__ W, int ldw,
    int m0, int n0, int k0,
    float* Asb, float* Bsb, int tid)
{
#pragma unroll
    for (int it = 0; it < 4; it++) {
        int idx = it * 256 + tid;
        int m = idx >> 3;
        int kg = idx & 7;
        CP_ASYNC16(smem_u32(&Asb[m * AS_STRIDE + kg * 4]),
                   X + (size_t)(m0 + m) * ldx + k0 + kg * 4);
    }
#pragma unroll
    for (int it = 0; it < 4; it++) {
        int idx = it * 256 + tid;
        int k = idx >> 5;
        int n4 = idx & 31;
        CP_ASYNC16(smem_u32(&Bsb[k * BS_STRIDE + n4 * 4]),
                   W + (size_t)(k0 + k) * ldw + n0 + n4 * 4);
    }
}

__device__ __forceinline__ void tf32_gemm_tile(
    const float* __restrict__ X, int ldx,
    const float* __restrict__ W, int ldw,
    int m0, int n0, int Ktot,
    float acc[4][4][4],
    float* As, float* Bs,
    int tid)
{
    const int lane = tid & 31;
    const int wid  = tid >> 5;
    const int wm   = wid & 1;
    const int wn   = wid >> 1;
    const int lr   = lane >> 2;
    const int lc   = lane & 3;
    const int nk   = Ktot >> 5;

    gemm_issue_loads(X, ldx, W, ldw, m0, n0, 0, As, Bs, tid);
    CP_COMMIT();

    for (int ki = 0; ki < nk; ki++) {
        if (ki + 1 < nk) {
            gemm_issue_loads(X, ldx, W, ldw, m0, n0, (ki + 1) * 32,
                             As + ((ki + 1) & 1) * AS_BUF,
                             Bs + ((ki + 1) & 1) * BS_BUF, tid);
            CP_COMMIT();
            CP_WAIT(1);
        } else {
            CP_WAIT(0);
        }
        __syncthreads();

        const float* Ac = As + (ki & 1) * AS_BUF;
        const float* Bc = Bs + (ki & 1) * BS_BUF;
#pragma unroll
        for (int kq = 0; kq < 4; kq++) {
            const int kk = kq * 8;
            uint32_t a[4][4], b[4][2];
#pragma unroll
            for (int mt = 0; mt < 4; mt++) {
                int base = (wm * 64 + mt * 16 + lr) * AS_STRIDE + kk + lc;
                a[mt][0] = __float_as_uint(Ac[base]);
                a[mt][1] = __float_as_uint(Ac[base + 8 * AS_STRIDE]);
                a[mt][2] = __float_as_uint(Ac[base + 4]);
                a[mt][3] = __float_as_uint(Ac[base + 8 * AS_STRIDE + 4]);
            }
#pragma unroll
            for (int nt = 0; nt < 4; nt++) {
                int bcol = wn * 32 + nt * 8 + lr;
                b[nt][0] = __float_as_uint(Bc[(kk + lc) * BS_STRIDE + bcol]);
                b[nt][1] = __float_as_uint(Bc[(kk + 4 + lc) * BS_STRIDE + bcol]);
            }
#pragma unroll
            for (int mt = 0; mt < 4; mt++)
#pragma unroll
                for (int nt = 0; nt < 4; nt++)
                    MMA_TF32(acc[mt][nt], a[mt], b[nt]);
        }
        __syncthreads();
    }
}

// ---------------------------------------------------------------------------
// Kernel 1: QKV GEMM; epilogue writes q,k,v as [b,h,t,d], tf32-rounded,
// softmax scale folded into q.
// ---------------------------------------------------------------------------
__global__ __launch_bounds__(256) void qkv_gemm_kernel(
    const float* __restrict__ bias)
{
    extern __shared__ float smg[];
    float* As = smg;
    float* Bs = smg + 2 * AS_BUF;
    const int tid = threadIdx.x;
    const int m0 = blockIdx.y * 128;
    const int n0 = blockIdx.x * 128;

    float acc[4][4][4];
#pragma unroll
    for (int i = 0; i < 4; i++)
#pragma unroll
        for (int j = 0; j < 4; j++)
#pragma unroll
            for (int q = 0; q < 4; q++) acc[i][j][q] = 0.f;

    tf32_gemm_tile(g_x, CH, g_wa, 3 * CH, m0, n0, CH, acc, As, Bs, tid);

    const int lane = tid & 31;
    const int wid  = tid >> 5;
    const int wm   = wid & 1;
    const int wn   = wid >> 1;
    const int lr   = lane >> 2;
    const int lc   = lane & 3;

    const int sec = n0 >> 10;  // 0=q 1=k 2=v
    float* dst = (sec == 0) ? g_q : (sec == 1 ? g_k : g_v);
    const float scale = (sec == 0) ? 0.125f : 1.0f;

#pragma unroll
    for (int mt = 0; mt < 4; mt++) {
        int r0 = m0 + wm * 64 + mt * 16 + lr;
        int bb = r0 >> 11;
        int t  = r0 & (SEQ - 1);
#pragma unroll
        for (int nt = 0; nt < 4; nt++) {
            int c0 = n0 + wn * 32 + nt * 8 + lc * 2;
            float b0 = bias[c0], b1 = bias[c0 + 1];
            int n1 = c0 & (CH - 1);
            int h  = n1 >> 6;
            int d  = n1 & 63;
            size_t base = ((size_t)((bb * NHEAD + h) * SEQ + t)) * HDIM + d;
            *reinterpret_cast<float2*>(&dst[base]) =
                make_float2(to_tf32((acc[mt][nt][0] + b0) * scale),
                            to_tf32((acc[mt][nt][1] + b1) * scale));
            *reinterpret_cast<float2*>(&dst[base + 8 * HDIM]) =
                make_float2(to_tf32((acc[mt][nt][2] + b0) * scale),
                            to_tf32((acc[mt][nt][3] + b1) * scale));
        }
    }
}

// ---------------------------------------------------------------------------
// Kernel 3: output projection
// ---------------------------------------------------------------------------
__global__ __launch_bounds__(256) void proj_gemm_kernel(
    const float* __restrict__ bias, float* __restrict__ out)
{
    extern __shared__ float smg[];
    float* As = smg;
    float* Bs = smg + 2 * AS_BUF;
    const int tid = threadIdx.x;
    const int m0 = blockIdx.y * 128;
    const int n0 = blockIdx.x * 128;

    float acc[4][4][4];
#pragma unroll
    for (int i = 0; i < 4; i++)
#pragma unroll
        for (int j = 0; j < 4; j++)
#pragma unroll
            for (int q = 0; q < 4; q++) acc[i][j][q] = 0.f;

    tf32_gemm_tile(g_att, CH, g_wp, CH, m0, n0, CH, acc, As, Bs, tid);

    const int lane = tid & 31;
    const int wid  = tid >> 5;
    const int wm   = wid & 1;
    const int wn   = wid >> 1;
    const int lr   = lane >> 2;
    const int lc   = lane & 3;

#pragma unroll
    for (int mt = 0; mt < 4; mt++) {
        int r0 = m0 + wm * 64 + mt * 16 + lr;
#pragma unroll
        for (int nt = 0; nt < 4; nt++) {
            int c0 = n0 + wn * 32 + nt * 8 + lc * 2;
            float b0 = bias[c0], b1 = bias[c0 + 1];
            *reinterpret_cast<float2*>(&out[(size_t)r0 * CH + c0]) =
                make_float2(acc[mt][nt][0] + b0, acc[mt][nt][1] + b1);
            *reinterpret_cast<float2*>(&out[(size_t)(r0 + 8) * CH + c0]) =
                make_float2(acc[mt][nt][2] + b0, acc[mt][nt][3] + b1);
        }
    }
}

// ---------------------------------------------------------------------------
// Kernel 2: causal flash attention, TF32 mma, cp.async double-buffered K/V.
// Block: 128 q-rows x 64 kv per iter; 8 warps, 16 q-rows each.
// ---------------------------------------------------------------------------
#define QS_STRIDE 68
#define VS_STRIDE 72
#define KS_BUF (64 * QS_STRIDE)
#define VS_BUF (64 * VS_STRIDE)
#define ATTN_SMEM ((128 * QS_STRIDE + 2 * KS_BUF + 2 * VS_BUF) * (int)sizeof(float))

__device__ __forceinline__ void attn_issue_kv(
    const float* __restrict__ kp, const float* __restrict__ vp,
    int k0, float* Ksb, float* Vsb, int tid)
{
#pragma unroll
    for (int it = 0; it < 4; it++) {
        int idx = it * 256 + tid;
        int row = idx >> 4;
        int c4  = (idx & 15) * 4;
        CP_ASYNC16(smem_u32(&Ksb[row * QS_STRIDE + c4]),
                   kp + (size_t)(k0 + row) * HDIM + c4);
        CP_ASYNC16(smem_u32(&Vsb[row * VS_STRIDE + c4]),
                   vp + (size_t)(k0 + row) * HDIM + c4);
    }
}

__global__ __launch_bounds__(256) void attn_kernel()
{
    extern __shared__ float sm[];
    float* Qs = sm;                          // [128][68]; later Pt (per warp)
    float* Ks = sm + 128 * QS_STRIDE;        // 2 x [64][68]
    float* Vs = Ks + 2 * KS_BUF;             // 2 x [64][72]

    const int tid  = threadIdx.x;
    const int lane = tid & 31;
    const int wq   = tid >> 5;
    const int lr   = lane >> 2;
    const int lc   = lane & 3;

    const int qt = (int)gridDim.x - 1 - (int)blockIdx.x;  // big tiles first
    const int bh = blockIdx.y;
    const int q0 = qt * 128;

    const float* qp = g_q + (size_t)bh * SEQ * HDIM;
    const float* kp = g_k + (size_t)bh * SEQ * HDIM;
    const float* vp = g_v + (size_t)bh * SEQ * HDIM;

    // Prologue: Q tile + first K/V tile in group 0
#pragma unroll
    for (int it = 0; it < 8; it++) {
        int idx = it * 256 + tid;
        int row = idx >> 4;
        int c4  = (idx & 15) * 4;
        CP_ASYNC16(smem_u32(&Qs[row * QS_STRIDE + c4]),
                   qp + (size_t)(q0 + row) * HDIM + c4);
    }
    attn_issue_kv(kp, vp, 0, Ks, Vs, tid);
    CP_COMMIT();

    uint32_t qf[8][4];
    float* Pt = Qs + wq * 16 * QS_STRIDE;   // per-warp 16x64 slab (own rows)

    float o[8][4] = {};
    float m0v = -1e30f, m1v = -1e30f;
    float l0v = 0.f, l1v = 0.f;

    const int nkt  = 2 * qt + 2;
    const int r_hi = q0 + wq * 16 + 15;

    for (int kt = 0; kt < nkt; kt++) {
        const int k0 = kt * 64;
        if (kt + 1 < nkt) {
            attn_issue_kv(kp, vp, (kt + 1) * 64,
                          Ks + ((kt + 1) & 1) * KS_BUF,
                          Vs + ((kt + 1) & 1) * VS_BUF, tid);
            CP_COMMIT();
            CP_WAIT(1);
        } else {
            CP_WAIT(0);
        }
        __syncthreads();

        if (kt == 0) {
            // Q fragments -> registers (already tf32-rounded at source)
            int rbase = (wq * 16 + lr) * QS_STRIDE;
#pragma unroll
            for (int s = 0; s < 8; s++) {
                qf[s][0] = __float_as_uint(Qs[rbase + s * 8 + lc]);
                qf[s][1] = __float_as_uint(Qs[rbase + 8 * QS_STRIDE + s * 8 + lc]);
                qf[s][2] = __float_as_uint(Qs[rbase + s * 8 + 4 + lc]);
                qf[s][3] = __float_as_uint(Qs[rbase + 8 * QS_STRIDE + s * 8 + 4 + lc]);
            }
        }

        if (k0 <= r_hi) {
            const float* Kc = Ks + (kt & 1) * KS_BUF;
            const float* Vc = Vs + (kt & 1) * VS_BUF;

            // ---- S = Q @ K^T ----
            float sacc[8][4];
#pragma unroll
            for (int nt = 0; nt < 8; nt++)
#pragma unroll
                for (int q = 0; q < 4; q++) sacc[nt][q] = 0.f;

#pragma unroll
            for (int s = 0; s < 8; s++) {
#pragma unroll
                for (int nt = 0; nt < 8; nt++) {
                    uint32_t b[2];
                    b[0] = __float_as_uint(Kc[(nt * 8 + lr) * QS_STRIDE + s * 8 + lc]);
                    b[1] = __float_as_uint(Kc[(nt * 8 + lr) * QS_STRIDE + s * 8 + 4 + lc]);
                    MMA_TF32(sacc[nt], qf[s], b);
                }
            }

            // ---- causal mask ----
            if (kt >= 2 * qt) {
                int r0g = q0 + wq * 16 + lr;
#pragma unroll
                for (int nt = 0; nt < 8; nt++) {
                    int c0g = k0 + nt * 8 + 2 * lc;
                    if (c0g     > r0g)     sacc[nt][0] = -1e30f;
                    if (c0g + 1 > r0g)     sacc[nt][1] = -1e30f;
                    if (c0g     > r0g + 8) sacc[nt][2] = -1e30f;
                    if (c0g + 1 > r0g + 8) sacc[nt][3] = -1e30f;
                }
            }

            // ---- online softmax ----
            float rm0 = -1e30f, rm1 = -1e30f;
#pragma unroll
            for (int nt = 0; nt < 8; nt++) {
                rm0 = fmaxf(rm0, fmaxf(sacc[nt][0], sacc[nt][1]));
                rm1 = fmaxf(rm1, fmaxf(sacc[nt][2], sacc[nt][3]));
            }
            rm0 = fmaxf(rm0, __shfl_xor_sync(0xffffffffu, rm0, 1));
            rm0 = fmaxf(rm0, __shfl_xor_sync(0xffffffffu, rm0, 2));
            rm1 = fmaxf(rm1, __shfl_xor_sync(0xffffffffu, rm1, 1));
            rm1 = fmaxf(rm1, __shfl_xor_sync(0xffffffffu, rm1, 2));

            float mn0 = fmaxf(m0v, rm0);
            float mn1 = fmaxf(m1v, rm1);
            float cr0 = __expf(m0v - mn0);
            float cr1 = __expf(m1v - mn1);
            m0v = mn0; m1v = mn1;

            float rs0 = 0.f, rs1 = 0.f;
#pragma unroll
            for (int nt = 0; nt < 8; nt++) {
                sacc[nt][0] = __expf(sacc[nt][0] - mn0);
                sacc[nt][1] = __expf(sacc[nt][1] - mn0);
                sacc[nt][2] = __expf(sacc[nt][2] - mn1);
                sacc[nt][3] = __expf(sacc[nt][3] - mn1);
                rs0 += sacc[nt][0] + sacc[nt][1];
                rs1 += sacc[nt][2] + sacc[nt][3];
            }
            rs0 += __shfl_xor_sync(0xffffffffu, rs0, 1);
            rs0 += __shfl_xor_sync(0xffffffffu, rs0, 2);
            rs1 += __shfl_xor_sync(0xffffffffu, rs1, 1);
            rs1 += __shfl_xor_sync(0xffffffffu, rs1, 2);
            l0v = l0v * cr0 + rs0;
            l1v = l1v * cr1 + rs1;
#pragma unroll
            for (int nt = 0; nt < 8; nt++) {
                o[nt][0] *= cr0; o[nt][1] *= cr0;
                o[nt][2] *= cr1; o[nt][3] *= cr1;
            }

            // ---- P -> per-warp smem slab (tf32-rounded) ----
#pragma unroll
            for (int nt = 0; nt < 8; nt++) {
                *reinterpret_cast<float2*>(&Pt[lr * QS_STRIDE + nt * 8 + 2 * lc]) =
                    make_float2(to_tf32(sacc[nt][0]), to_tf32(sacc[nt][1]));
                *reinterpret_cast<float2*>(&Pt[(lr + 8) * QS_STRIDE + nt * 8 + 2 * lc]) =
                    make_float2(to_tf32(sacc[nt][2]), to_tf32(sacc[nt][3]));
            }
            __syncwarp();

            // ---- O += P @ V ----
#pragma unroll
            for (int s = 0; s < 8; s++) {
                uint32_t a[4];
                a[0] = __float_as_uint(Pt[lr * QS_STRIDE + s * 8 + lc]);
                a[1] = __float_as_uint(Pt[(lr + 8) * QS_STRIDE + s * 8 + lc]);
                a[2] = __float_as_uint(Pt[lr * QS_STRIDE + s * 8 + 4 + lc]);
                a[3] = __float_as_uint(Pt[(lr + 8) * QS_STRIDE + s * 8 + 4 + lc]);
#pragma unroll
                for (int nt = 0; nt < 8; nt++) {
                    uint32_t b[2];
                    b[0] = __float_as_uint(Vc[(s * 8 + lc) * VS_STRIDE + nt * 8 + lr]);
                    b[1] = __float_as_uint(Vc[(s * 8 + 4 + lc) * VS_STRIDE + nt * 8 + lr]);
                    MMA_TF32(o[nt], a, b);
                }
            }
        }
        __syncthreads();  // all K/V reads done before next prefetch overwrites
    }

    // ---- normalize + store to [b,t,c] (tf32-rounded: feeds proj GEMM) ----
    const int b = bh >> 4, h = bh & 15;
    const int r0g = q0 + wq * 16 + lr;
    const float inv0 = 1.0f / l0v;
    const float inv1 = 1.0f / l1v;
#pragma unroll
    for (int nt = 0; nt < 8; nt++) {
        int cg = h * 64 + nt * 8 + 2 * lc;
        *reinterpret_cast<float2*>(&g_att[(size_t)(b * SEQ + r0g) * CH + cg]) =
            make_float2(to_tf32(o[nt][0] * inv0), to_tf32(o[nt][1] * inv0));
        *reinterpret_cast<float2*>(&g_att[(size_t)(b * SEQ + r0g + 8) * CH + cg]) =
            make_float2(to_tf32(o[nt][2] * inv1), to_tf32(o[nt][3] * inv1));
    }
}

// ---------------------------------------------------------------------------
extern "C" void kernel_launch(void* const* d_in, const int* in_sizes, int n_in,
                              void* d_out, int out_size)
{
    const float* x      = (const float*)d_in[0];
    const float* w_attn = (const float*)d_in[1];
    const float* b_attn = (const float*)d_in[2];
    const float* w_proj = (const float*)d_in[3];
    const float* b_proj = (const float*)d_in[4];
    float* out = (float*)d_out;

    cudaFuncSetAttribute(qkv_gemm_kernel,
                         cudaFuncAttributeMaxDynamicSharedMemorySize, GEMM_SMEM);
    cudaFuncSetAttribute(proj_gemm_kernel,
                         cudaFuncAttributeMaxDynamicSharedMemorySize, GEMM_SMEM);
    cudaFuncSetAttribute(attn_kernel,
                         cudaFuncAttributeMaxDynamicSharedMemorySize, ATTN_SMEM);

    // 0) tf32-round inputs
    cvt_tf32_kernel<<<(BATCH * SEQ * CH / 4 + 255) / 256, 256>>>(x, 0,
        BATCH * SEQ * CH / 4);
    cvt_tf32_kernel<<<(CH * 3 * CH / 4 + 255) / 256, 256>>>(w_attn, 1,
        CH * 3 * CH / 4);
    cvt_tf32_kernel<<<(CH * CH / 4 + 255) / 256, 256>>>(w_proj, 2,
        CH * CH / 4);

    // 1) QKV GEMM: grid (3072/128, 8192/128)
    qkv_gemm_kernel<<<dim3(24, 64), 256, GEMM_SMEM>>>(b_attn);

    // 2) Attention: grid (16 q-tiles, B*NH)
    attn_kernel<<<dim3(16, BATCH * NHEAD), 256, ATTN_SMEM>>>();

    // 3) Projection: grid (1024/128, 8192/128)
    proj_gemm_kernel<<<dim3(8, 64), 256, GEMM_SMEM>>>(b_proj, out);
}

// round 6
// speedup vs baseline: 3.3938x; 1.0120x over previous
#include <cuda_runtime.h>
#include <cstdint>

#define BATCH 4
#define SEQ   2048
#define CH    1024
#define NHEAD 16
#define HDIM  64

// Scratch (allocation-free rule: __device__ globals).
// q,k: [b,h,t,d]; v: [b,h,d,t] (transposed for PV ldmatrix).
__device__ float g_q[BATCH * NHEAD * SEQ * HDIM];
__device__ float g_k[BATCH * NHEAD * SEQ * HDIM];
__device__ float g_v[BATCH * NHEAD * HDIM * SEQ];
__device__ float g_att[BATCH * SEQ * CH];        // [b,t,c], tf32-rounded
__device__ float g_x [BATCH * SEQ * CH];         // x, tf32-rounded
__device__ float g_wa[3 * CH * CH];              // w_attn^T: [3072][1024], tf32
__device__ float g_wp[CH * CH];                  // w_proj^T: [1024][1024], tf32

__device__ __forceinline__ float to_tf32(float x) {
    float r;
    asm("cvt.rna.tf32.f32 %0, %1;" : "=f"(r) : "f"(x));
    return r;
}

#define MMA_TF32(d, a, b)                                                  \
    asm volatile(                                                          \
        "mma.sync.aligned.m16n8k8.row.col.f32.tf32.tf32.f32 "              \
        "{%0,%1,%2,%3},{%4,%5,%6,%7},{%8,%9},{%0,%1,%2,%3};"               \
        : "+f"((d)[0]), "+f"((d)[1]), "+f"((d)[2]), "+f"((d)[3])           \
        : "r"((a)[0]), "r"((a)[1]), "r"((a)[2]), "r"((a)[3]),              \
          "r"((b)[0]), "r"((b)[1]))

// ldmatrix x4 on b16 8x8 tiles == 8x4 fp32 blocks (tf32 fragment layout).
#define LDM_X4(r, addr)                                                    \
    asm volatile("ldmatrix.sync.aligned.m8n8.x4.shared.b16 "               \
                 "{%0,%1,%2,%3}, [%4];"                                    \
                 : "=r"((r)[0]), "=r"((r)[1]), "=r"((r)[2]), "=r"((r)[3])  \
                 : "r"(addr))

#define CP_ASYNC16(dst_u32, src_ptr)                                       \
    asm volatile("cp.async.cg.shared.global [%0], [%1], 16;"               \
                 :: "r"(dst_u32), "l"(src_ptr))
#define CP_COMMIT() asm volatile("cp.async.commit_group;")
#define CP_WAIT(N)  asm volatile("cp.async.wait_group %0;" :: "n"(N))

__device__ __forceinline__ uint32_t smem_u32(const void* p) {
    return (uint32_t)__cvta_generic_to_shared(p);
}

// ---------------------------------------------------------------------------
// Prologue converts
// ---------------------------------------------------------------------------
__global__ void cvt_x_kernel(const float* __restrict__ src, int n4)
{
    int i = blockIdx.x * blockDim.x + threadIdx.x;
    if (i < n4) {
        float4 v = reinterpret_cast<const float4*>(src)[i];
        v.x = to_tf32(v.x); v.y = to_tf32(v.y);
        v.z = to_tf32(v.z); v.w = to_tf32(v.w);
        reinterpret_cast<float4*>(g_x)[i] = v;
    }
}

// Transpose + tf32-round weights: src [CH][N] -> dst [N][CH]
__global__ void cvt_T_kernel(const float* __restrict__ src, int sel, int N)
{
    __shared__ float tile[32][33];
    float* dst = (sel == 1) ? g_wa : g_wp;
    int n0 = blockIdx.x * 32, k0 = blockIdx.y * 32;
    int tx = threadIdx.x, ty = threadIdx.y;  // 32 x 8
#pragma unroll
    for (int i = 0; i < 4; i++)
        tile[ty + 8 * i][tx] = src[(size_t)(k0 + ty + 8 * i) * N + n0 + tx];
    __syncthreads();
#pragma unroll
    for (int i = 0; i < 4; i++)
        dst[(size_t)(n0 + ty + 8 * i) * CH + k0 + tx] = to_tf32(tile[tx][ty + 8 * i]);
}

// ---------------------------------------------------------------------------
// TF32 GEMM core: block 128x128, BK=32, 8 warps (2x4), warp tile 64x32.
// A smem [128][36] (m rows, k contig); B smem [128][36] (n rows, k contig).
// Fragments via ldmatrix.x4; cp.async double-buffered.
// ---------------------------------------------------------------------------
#define GS 36                      // smem row stride (floats)
#define GBUF (128 * GS)            // floats per buffer
#define GEMM_SMEM (4 * GBUF * (int)sizeof(float))   // 73728 B

__device__ __forceinline__ void gemm_issue_loads(
    const float* __restrict__ A, const float* __restrict__ B,
    int m0, int n0, int k0, uint32_t sA, uint32_t sB, int tid)
{
#pragma unroll
    for (int it = 0; it < 4; it++) {
        int idx = it * 256 + tid;
        int row = idx >> 3, c = idx & 7;
        CP_ASYNC16(sA + row * (GS * 4) + c * 16,
                   A + (size_t)(m0 + row) * CH + k0 + c * 4);
    }
#pragma unroll
    for (int it = 0; it < 4; it++) {
        int idx = it * 256 + tid;
        int row = idx >> 3, c = idx & 7;
        CP_ASYNC16(sB + row * (GS * 4) + c * 16,
                   B + (size_t)(n0 + row) * CH + k0 + c * 4);
    }
}

__device__ __forceinline__ void tf32_gemm_tile(
    const float* __restrict__ A, const float* __restrict__ B,
    int m0, int n0,
    float acc[4][4][4],
    uint32_t sbase, int tid)
{
    const int lane  = tid & 31;
    const int wid   = tid >> 5;
    const int wm    = wid & 1;
    const int wn    = wid >> 1;
    const int lane8 = lane & 7;
    const int laneh = (lane >> 3) & 1;
    const int laneq = lane >> 4;

    const uint32_t sA0 = sbase;
    const uint32_t sB0 = sbase + 2 * GBUF * 4;

    // per-lane ldmatrix offsets (bytes, within a buffer)
    // A x4 (mt, kq): row = wm*64+mt*16 + lane8 + laneh*8 ; col = kq*8 + laneq*4
    const uint32_t a_lm =
        ((wm * 64 + lane8 + laneh * 8) * GS + laneq * 4) * 4;
    // B x4 (nt, kq-pair): row = wn*32+nt*8 + lane8 ; col = kq2*16 + (lane>>3)*4
    const uint32_t b_lm =
        ((wn * 32 + lane8) * GS + (lane >> 3) * 4) * 4;

    gemm_issue_loads(A, B, m0, n0, 0, sA0, sB0, tid);
    CP_COMMIT();

    const int nk = CH / 32;
    for (int ki = 0; ki < nk; ki++) {
        if (ki + 1 < nk) {
            gemm_issue_loads(A, B, m0, n0, (ki + 1) * 32,
                             sA0 + ((ki + 1) & 1) * GBUF * 4,
                             sB0 + ((ki + 1) & 1) * GBUF * 4, tid);
            CP_COMMIT();
            CP_WAIT(1);
        } else {
            CP_WAIT(0);
        }
        __syncthreads();

        const uint32_t Ab = sA0 + (ki & 1) * GBUF * 4;
        const uint32_t Bb = sB0 + (ki & 1) * GBUF * 4;

        uint32_t bf[4][4];
#pragma unroll
        for (int kq = 0; kq < 4; kq++) {
            if ((kq & 1) == 0) {
#pragma unroll
                for (int nt = 0; nt < 4; nt++)
                    LDM_X4(bf[nt], Bb + b_lm + nt * (8 * GS * 4) + (kq >> 1) * 64);
            }
#pragma unroll
            for (int mt = 0; mt < 4; mt++) {
                uint32_t af[4];
                LDM_X4(af, Ab + a_lm + mt * (16 * GS * 4) + kq * 32);
#pragma unroll
                for (int nt = 0; nt < 4; nt++)
                    MMA_TF32(acc[mt][nt], af, &bf[nt][(kq & 1) * 2]);
            }
        }
        __syncthreads();
    }
}

// ---------------------------------------------------------------------------
// Kernel 1: QKV GEMM; writes q,k [b,h,t,d] and v [b,h,d,t], tf32-rounded,
// softmax scale folded into q.
// ---------------------------------------------------------------------------
__global__ __launch_bounds__(256) void qkv_gemm_kernel(
    const float* __restrict__ bias)
{
    extern __shared__ float smg[];
    const uint32_t sbase = smem_u32(smg);
    const int tid = threadIdx.x;
    const int m0 = blockIdx.y * 128;
    const int n0 = blockIdx.x * 128;

    float acc[4][4][4];
#pragma unroll
    for (int i = 0; i < 4; i++)
#pragma unroll
        for (int j = 0; j < 4; j++)
#pragma unroll
            for (int q = 0; q < 4; q++) acc[i][j][q] = 0.f;

    tf32_gemm_tile(g_x, g_wa, m0, n0, acc, sbase, tid);

    const int lane = tid & 31;
    const int wid  = tid >> 5;
    const int wm   = wid & 1;
    const int wn   = wid >> 1;
    const int lr   = lane >> 2;
    const int lc   = lane & 3;

    const int sec = n0 >> 10;  // 0=q 1=k 2=v
    const float scale = (sec == 0) ? 0.125f : 1.0f;

#pragma unroll
    for (int mt = 0; mt < 4; mt++) {
        int r0 = m0 + wm * 64 + mt * 16 + lr;
        int bb = r0 >> 11;
        int t  = r0 & (SEQ - 1);
#pragma unroll
        for (int nt = 0; nt < 4; nt++) {
            int c0 = n0 + wn * 32 + nt * 8 + lc * 2;
            float b0 = bias[c0], b1 = bias[c0 + 1];
            int n1 = c0 & (CH - 1);
            int h  = n1 >> 6;
            int d  = n1 & 63;
            float v00 = to_tf32((acc[mt][nt][0] + b0) * scale);
            float v01 = to_tf32((acc[mt][nt][1] + b1) * scale);
            float v10 = to_tf32((acc[mt][nt][2] + b0) * scale);
            float v11 = to_tf32((acc[mt][nt][3] + b1) * scale);
            if (sec < 2) {
                float* dst = (sec == 0) ? g_q : g_k;
                size_t base = ((size_t)((bb * NHEAD + h) * SEQ + t)) * HDIM + d;
                *reinterpret_cast<float2*>(&dst[base]) = make_float2(v00, v01);
                *reinterpret_cast<float2*>(&dst[base + 8 * HDIM]) =
                    make_float2(v10, v11);
            } else {
                // v transposed: [b,h,d,t]
                size_t base = ((size_t)((bb * NHEAD + h) * HDIM + d)) * SEQ + t;
                g_v[base]           = v00;
                g_v[base + SEQ]     = v01;   // d+1
                g_v[base + 8]       = v10;   // t+8
                g_v[base + SEQ + 8] = v11;
            }
        }
    }
}

// ---------------------------------------------------------------------------
// Kernel 3: output projection
// ---------------------------------------------------------------------------
__global__ __launch_bounds__(256) void proj_gemm_kernel(
    const float* __restrict__ bias, float* __restrict__ out)
{
    extern __shared__ float smg[];
    const uint32_t sbase = smem_u32(smg);
    const int tid = threadIdx.x;
    const int m0 = blockIdx.y * 128;
    const int n0 = blockIdx.x * 128;

    float acc[4][4][4];
#pragma unroll
    for (int i = 0; i < 4; i++)
#pragma unroll
        for (int j = 0; j < 4; j++)
#pragma unroll
            for (int q = 0; q < 4; q++) acc[i][j][q] = 0.f;

    tf32_gemm_tile(g_att, g_wp, m0, n0, acc, sbase, tid);

    const int lane = tid & 31;
    const int wid  = tid >> 5;
    const int wm   = wid & 1;
    const int wn   = wid >> 1;
    const int lr   = lane >> 2;
    const int lc   = lane & 3;

#pragma unroll
    for (int mt = 0; mt < 4; mt++) {
        int r0 = m0 + wm * 64 + mt * 16 + lr;
#pragma unroll
        for (int nt = 0; nt < 4; nt++) {
            int c0 = n0 + wn * 32 + nt * 8 + lc * 2;
            float b0 = bias[c0], b1 = bias[c0 + 1];
            *reinterpret_cast<float2*>(&out[(size_t)r0 * CH + c0]) =
                make_float2(acc[mt][nt][0] + b0, acc[mt][nt][1] + b1);
            *reinterpret_cast<float2*>(&out[(size_t)(r0 + 8) * CH + c0]) =
                make_float2(acc[mt][nt][2] + b0, acc[mt][nt][3] + b1);
        }
    }
}

// ---------------------------------------------------------------------------
// Kernel 2: causal flash attention, TF32 mma.sync + ldmatrix fragments,
// cp.async double-buffered K/V. Block: 128 q x 64 kv; 8 warps x 16 q rows.
// K smem [t][68]; V smem [d][68] (v already [b,h,d,t] in gmem);
// P per-warp slab aliased on Q smem.
// ---------------------------------------------------------------------------
#define AST 68                     // attention smem row stride (floats)
#define KV_BUF (64 * AST)
#define ATTN_SMEM ((128 * AST + 4 * KV_BUF) * (int)sizeof(float))

__device__ __forceinline__ void attn_issue_kv(
    const float* __restrict__ kp, const float* __restrict__ vp,
    int k0, uint32_t sK, uint32_t sV, int tid)
{
#pragma unroll
    for (int it = 0; it < 4; it++) {
        int idx = it * 256 + tid;
        int row = idx >> 4;
        int c4  = (idx & 15) * 4;
        CP_ASYNC16(sK + row * (AST * 4) + c4 * 4,
                   kp + (size_t)(k0 + row) * HDIM + c4);
        // V: rows are d (64), cols are t within the kv tile
        CP_ASYNC16(sV + row * (AST * 4) + c4 * 4,
                   vp + (size_t)row * SEQ + k0 + c4);
    }
}

__global__ __launch_bounds__(256) void attn_kernel()
{
    extern __shared__ float sm[];
    const uint32_t sbase = smem_u32(sm);
    const uint32_t sQs = sbase;
    const uint32_t sKs = sbase + 128 * AST * 4;
    const uint32_t sVs = sKs + 2 * KV_BUF * 4;

    const int tid   = threadIdx.x;
    const int lane  = tid & 31;
    const int wq    = tid >> 5;
    const int lr    = lane >> 2;
    const int lc    = lane & 3;
    const int lane8 = lane & 7;
    const int laneh = (lane >> 3) & 1;
    const int laneq = lane >> 4;

    const int qt = (int)gridDim.x - 1 - (int)blockIdx.x;  // big tiles first
    const int bh = blockIdx.y;
    const int q0 = qt * 128;

    const float* qp = g_q + (size_t)bh * SEQ * HDIM;
    const float* kp = g_k + (size_t)bh * SEQ * HDIM;
    const float* vp = g_v + (size_t)bh * HDIM * SEQ;

    // ldmatrix per-lane byte offsets
    const uint32_t q_lm = sQs +
        ((wq * 16 + lane8 + laneh * 8) * AST + laneq * 4) * 4;        // + kq*32
    const uint32_t k_lm = (lane8 * AST + (lane >> 3) * 4) * 4;        // + nt*8rows + s2*64
    const uint32_t p_lm = ((lane8 + laneh * 8) * AST + laneq * 4) * 4; // + s*32
    const uint32_t v_lm = ((laneq * 8 + lane8) * AST + laneh * 4) * 4; // + dp*16rows + s*32

    // Prologue: Q tile + first K/V tile
#pragma unroll
    for (int it = 0; it < 8; it++) {
        int idx = it * 256 + tid;
        int row = idx >> 4;
        int c4  = (idx & 15) * 4;
        CP_ASYNC16(sQs + row * (AST * 4) + c4 * 4,
                   qp + (size_t)(q0 + row) * HDIM + c4);
    }
    attn_issue_kv(kp, vp, 0, sKs, sVs, tid);
    CP_COMMIT();

    uint32_t qf[8][4];
    const uint32_t sPt = sQs + wq * 16 * AST * 4;   // per-warp 16x64 slab
    float* Pt = sm + wq * 16 * AST;

    float o[8][4] = {};
    float m0v = -1e30f, m1v = -1e30f;
    float l0v = 0.f, l1v = 0.f;

    const int nkt  = 2 * qt + 2;
    const int r_hi = q0 + wq * 16 + 15;

    for (int kt = 0; kt < nkt; kt++) {
        const int k0 = kt * 64;
        if (kt + 1 < nkt) {
            attn_issue_kv(kp, vp, (kt + 1) * 64,
                          sKs + ((kt + 1) & 1) * KV_BUF * 4,
                          sVs + ((kt + 1) & 1) * KV_BUF * 4, tid);
            CP_COMMIT();
            CP_WAIT(1);
        } else {
            CP_WAIT(0);
        }
        __syncthreads();

        if (kt == 0) {
#pragma unroll
            for (int s = 0; s < 8; s++)
                LDM_X4(qf[s], q_lm + s * 32);
        }

        if (k0 <= r_hi) {
            const uint32_t Kb = sKs + (kt & 1) * KV_BUF * 4;
            const uint32_t Vb = sVs + (kt & 1) * KV_BUF * 4;

            // ---- S = Q @ K^T : 64 mmas, K b-frags via ldmatrix ----
            float sacc[8][4];
#pragma unroll
            for (int nt = 0; nt < 8; nt++)
#pragma unroll
                for (int q = 0; q < 4; q++) sacc[nt][q] = 0.f;

#pragma unroll
            for (int s2 = 0; s2 < 4; s2++) {
                uint32_t bf[8][4];
#pragma unroll
                for (int nt = 0; nt < 8; nt++)
                    LDM_X4(bf[nt], Kb + k_lm + nt * (8 * AST * 4) + s2 * 64);
#pragma unroll
                for (int sub = 0; sub < 2; sub++)
#pragma unroll
                    for (int nt = 0; nt < 8; nt++)
                        MMA_TF32(sacc[nt], qf[2 * s2 + sub], &bf[nt][sub * 2]);
            }

            // ---- causal mask ----
            if (kt >= 2 * qt) {
                int r0g = q0 + wq * 16 + lr;
#pragma unroll
                for (int nt = 0; nt < 8; nt++) {
                    int c0g = k0 + nt * 8 + 2 * lc;
                    if (c0g     > r0g)     sacc[nt][0] = -1e30f;
                    if (c0g + 1 > r0g)     sacc[nt][1] = -1e30f;
                    if (c0g     > r0g + 8) sacc[nt][2] = -1e30f;
                    if (c0g + 1 > r0g + 8) sacc[nt][3] = -1e30f;
                }
            }

            // ---- online softmax ----
            float rm0 = -1e30f, rm1 = -1e30f;
#pragma unroll
            for (int nt = 0; nt < 8; nt++) {
                rm0 = fmaxf(rm0, fmaxf(sacc[nt][0], sacc[nt][1]));
                rm1 = fmaxf(rm1, fmaxf(sacc[nt][2], sacc[nt][3]));
            }
            rm0 = fmaxf(rm0, __shfl_xor_sync(0xffffffffu, rm0, 1));
            rm0 = fmaxf(rm0, __shfl_xor_sync(0xffffffffu, rm0, 2));
            rm1 = fmaxf(rm1, __shfl_xor_sync(0xffffffffu, rm1, 1));
            rm1 = fmaxf(rm1, __shfl_xor_sync(0xffffffffu, rm1, 2));

            float mn0 = fmaxf(m0v, rm0);
            float mn1 = fmaxf(m1v, rm1);
            float cr0 = __expf(m0v - mn0);
            float cr1 = __expf(m1v - mn1);
            m0v = mn0; m1v = mn1;

            float rs0 = 0.f, rs1 = 0.f;
#pragma unroll
            for (int nt = 0; nt < 8; nt++) {
                sacc[nt][0] = __expf(sacc[nt][0] - mn0);
                sacc[nt][1] = __expf(sacc[nt][1] - mn0);
                sacc[nt][2] = __expf(sacc[nt][2] - mn1);
                sacc[nt][3] = __expf(sacc[nt][3] - mn1);
                rs0 += sacc[nt][0] + sacc[nt][1];
                rs1 += sacc[nt][2] + sacc[nt][3];
            }
            rs0 += __shfl_xor_sync(0xffffffffu, rs0, 1);
            rs0 += __shfl_xor_sync(0xffffffffu, rs0, 2);
            rs1 += __shfl_xor_sync(0xffffffffu, rs1, 1);
            rs1 += __shfl_xor_sync(0xffffffffu, rs1, 2);
            l0v = l0v * cr0 + rs0;
            l1v = l1v * cr1 + rs1;
#pragma unroll
            for (int nt = 0; nt < 8; nt++) {
                o[nt][0] *= cr0; o[nt][1] *= cr0;
                o[nt][2] *= cr1; o[nt][3] *= cr1;
            }

            // ---- P -> per-warp smem slab (tf32-rounded) ----
#pragma unroll
            for (int nt = 0; nt < 8; nt++) {
                *reinterpret_cast<float2*>(&Pt[lr * AST + nt * 8 + 2 * lc]) =
                    make_float2(to_tf32(sacc[nt][0]), to_tf32(sacc[nt][1]));
                *reinterpret_cast<float2*>(&Pt[(lr + 8) * AST + nt * 8 + 2 * lc]) =
                    make_float2(to_tf32(sacc[nt][2]), to_tf32(sacc[nt][3]));
            }
            __syncwarp();

            // ---- O += P @ V : 64 mmas, all frags via ldmatrix ----
#pragma unroll
            for (int s = 0; s < 8; s++) {
                uint32_t a[4];
                LDM_X4(a, sPt + p_lm + s * 32);
#pragma unroll
                for (int dp = 0; dp < 4; dp++) {
                    uint32_t b[4];
                    LDM_X4(b, Vb + v_lm + dp * (16 * AST * 4) + s * 32);
                    MMA_TF32(o[2 * dp],     a, &b[0]);
                    MMA_TF32(o[2 * dp + 1], a, &b[2]);
                }
            }
            __syncwarp();
        }
        __syncthreads();
    }

    // ---- normalize + store to [b,t,c] (tf32-rounded: feeds proj) ----
    const int b = bh >> 4, h = bh & 15;
    const int r0g = q0 + wq * 16 + lr;
    const float inv0 = 1.0f / l0v;
    const float inv1 = 1.0f / l1v;
#pragma unroll
    for (int nt = 0; nt < 8; nt++) {
        int cg = h * 64 + nt * 8 + 2 * lc;
        *reinterpret_cast<float2*>(&g_att[(size_t)(b * SEQ + r0g) * CH + cg]) =
            make_float2(to_tf32(o[nt][0] * inv0), to_tf32(o[nt][1] * inv0));
        *reinterpret_cast<float2*>(&g_att[(size_t)(b * SEQ + r0g + 8) * CH + cg]) =
            make_float2(to_tf32(o[nt][2] * inv1), to_tf32(o[nt][3] * inv1));
    }
}

// ---------------------------------------------------------------------------
extern "C" void kernel_launch(void* const* d_in, const int* in_sizes, int n_in,
                              void* d_out, int out_size)
{
    const float* x      = (const float*)d_in[0];
    const float* w_attn = (const float*)d_in[1];
    const float* b_attn = (const float*)d_in[2];
    const float* w_proj = (const float*)d_in[3];
    const float* b_proj = (const float*)d_in[4];
    float* out = (float*)d_out;

    cudaFuncSetAttribute(qkv_gemm_kernel,
                         cudaFuncAttributeMaxDynamicSharedMemorySize, GEMM_SMEM);
    cudaFuncSetAttribute(proj_gemm_kernel,
                         cudaFuncAttributeMaxDynamicSharedMemorySize, GEMM_SMEM);
    cudaFuncSetAttribute(attn_kernel,
                         cudaFuncAttributeMaxDynamicSharedMemorySize, ATTN_SMEM);

    // 0) tf32-round x; transpose+round weights to [N][K]
    cvt_x_kernel<<<(BATCH * SEQ * CH / 4 + 255) / 256, 256>>>(x,
        BATCH * SEQ * CH / 4);
    cvt_T_kernel<<<dim3(3 * CH / 32, CH / 32), dim3(32, 8)>>>(w_attn, 1, 3 * CH);
    cvt_T_kernel<<<dim3(CH / 32, CH / 32), dim3(32, 8)>>>(w_proj, 2, CH);

    // 1) QKV GEMM: grid (3072/128, 8192/128)
    qkv_gemm_kernel<<<dim3(24, 64), 256, GEMM_SMEM>>>(b_attn);

    // 2) Attention: grid (16 q-tiles, B*NH)
    attn_kernel<<<dim3(16, BATCH * NHEAD), 256, ATTN_SMEM>>>();

    // 3) Projection: grid (1024/128, 8192/128)
    proj_gemm_kernel<<<dim3(8, 64), 256, GEMM_SMEM>>>(b_proj, out);
}

// round 7
// speedup vs baseline: 3.6215x; 1.0671x over previous
#include <cuda_runtime.h>
#include <cstdint>

#define BATCH 4
#define SEQ   2048
#define CH    1024
#define NHEAD 16
#define HDIM  64

// Scratch (allocation-free rule: __device__ globals).
// q,k: [b,h,t,d]; v: [b,h,d,t] (transposed for PV ldmatrix).
__device__ float g_q[BATCH * NHEAD * SEQ * HDIM];
__device__ float g_k[BATCH * NHEAD * SEQ * HDIM];
__device__ float g_v[BATCH * NHEAD * HDIM * SEQ];
__device__ float g_att[BATCH * SEQ * CH];        // [b,t,c], tf32-rounded
__device__ float g_x [BATCH * SEQ * CH];         // x, tf32-rounded
__device__ float g_wa[3 * CH * CH];              // w_attn^T: [3072][1024], tf32
__device__ float g_wp[CH * CH];                  // w_proj^T: [1024][1024], tf32

__device__ __forceinline__ float to_tf32(float x) {
    float r;
    asm("cvt.rna.tf32.f32 %0, %1;" : "=f"(r) : "f"(x));
    return r;
}

#define MMA_TF32(d, a, b)                                                  \
    asm volatile(                                                          \
        "mma.sync.aligned.m16n8k8.row.col.f32.tf32.tf32.f32 "              \
        "{%0,%1,%2,%3},{%4,%5,%6,%7},{%8,%9},{%0,%1,%2,%3};"               \
        : "+f"((d)[0]), "+f"((d)[1]), "+f"((d)[2]), "+f"((d)[3])           \
        : "r"((a)[0]), "r"((a)[1]), "r"((a)[2]), "r"((a)[3]),              \
          "r"((b)[0]), "r"((b)[1]))

// ldmatrix x4 on b16 8x8 tiles == 8x4 fp32 blocks (tf32 fragment layout).
#define LDM_X4(r, addr)                                                    \
    asm volatile("ldmatrix.sync.aligned.m8n8.x4.shared.b16 "               \
                 "{%0,%1,%2,%3}, [%4];"                                    \
                 : "=r"((r)[0]), "=r"((r)[1]), "=r"((r)[2]), "=r"((r)[3])  \
                 : "r"(addr))

#define CP_ASYNC16(dst_u32, src_ptr)                                       \
    asm volatile("cp.async.cg.shared.global [%0], [%1], 16;"               \
                 :: "r"(dst_u32), "l"(src_ptr))
#define CP_COMMIT() asm volatile("cp.async.commit_group;")
#define CP_WAIT(N)  asm volatile("cp.async.wait_group %0;" :: "n"(N))

__device__ __forceinline__ uint32_t smem_u32(const void* p) {
    return (uint32_t)__cvta_generic_to_shared(p);
}

// ---------------------------------------------------------------------------
// Prologue converts
// ---------------------------------------------------------------------------
__global__ void cvt_x_kernel(const float* __restrict__ src, int n4)
{
    int i = blockIdx.x * blockDim.x + threadIdx.x;
    if (i < n4) {
        float4 v = reinterpret_cast<const float4*>(src)[i];
        v.x = to_tf32(v.x); v.y = to_tf32(v.y);
        v.z = to_tf32(v.z); v.w = to_tf32(v.w);
        reinterpret_cast<float4*>(g_x)[i] = v;
    }
}

// Transpose + tf32-round weights: src [CH][N] -> dst [N][CH]
__global__ void cvt_T_kernel(const float* __restrict__ src, int sel, int N)
{
    __shared__ float tile[32][33];
    float* dst = (sel == 1) ? g_wa : g_wp;
    int n0 = blockIdx.x * 32, k0 = blockIdx.y * 32;
    int tx = threadIdx.x, ty = threadIdx.y;  // 32 x 8
#pragma unroll
    for (int i = 0; i < 4; i++)
        tile[ty + 8 * i][tx] = src[(size_t)(k0 + ty + 8 * i) * N + n0 + tx];
    __syncthreads();
#pragma unroll
    for (int i = 0; i < 4; i++)
        dst[(size_t)(n0 + ty + 8 * i) * CH + k0 + tx] = to_tf32(tile[tx][ty + 8 * i]);
}

// ---------------------------------------------------------------------------
// TF32 GEMM core: block 128x128, BK=32, 8 warps (2x4), warp tile 64x32.
// 3-stage cp.async pipeline, ONE barrier per slab.
// A smem [128][36] (m rows, k contig); B smem [128][36] (n rows, k contig).
// ---------------------------------------------------------------------------
#define GS 36                      // smem row stride (floats)
#define GBUF (128 * GS)            // floats per buffer
#define NSTAGE 3
#define GEMM_SMEM (2 * NSTAGE * GBUF * (int)sizeof(float))   // 110592 B

__device__ __forceinline__ void gemm_issue_loads(
    const float* __restrict__ A, const float* __restrict__ B,
    int m0, int n0, int k0, uint32_t sA, uint32_t sB, int tid)
{
#pragma unroll
    for (int it = 0; it < 4; it++) {
        int idx = it * 256 + tid;
        int row = idx >> 3, c = idx & 7;
        CP_ASYNC16(sA + row * (GS * 4) + c * 16,
                   A + (size_t)(m0 + row) * CH + k0 + c * 4);
    }
#pragma unroll
    for (int it = 0; it < 4; it++) {
        int idx = it * 256 + tid;
        int row = idx >> 3, c = idx & 7;
        CP_ASYNC16(sB + row * (GS * 4) + c * 16,
                   B + (size_t)(n0 + row) * CH + k0 + c * 4);
    }
}

__device__ __forceinline__ void tf32_gemm_tile(
    const float* __restrict__ A, const float* __restrict__ B,
    int m0, int n0,
    float acc[4][4][4],
    uint32_t sbase, int tid)
{
    const int lane  = tid & 31;
    const int wid   = tid >> 5;
    const int wm    = wid & 1;
    const int wn    = wid >> 1;
    const int lane8 = lane & 7;
    const int laneh = (lane >> 3) & 1;
    const int laneq = lane >> 4;

    const uint32_t sA0 = sbase;
    const uint32_t sB0 = sbase + NSTAGE * GBUF * 4;

    // per-lane ldmatrix offsets (bytes, within a buffer)
    const uint32_t a_lm =
        ((wm * 64 + lane8 + laneh * 8) * GS + laneq * 4) * 4;
    const uint32_t b_lm =
        ((wn * 32 + lane8) * GS + (lane >> 3) * 4) * 4;

    // Prologue: stages 0 and 1 in flight
    gemm_issue_loads(A, B, m0, n0, 0, sA0, sB0, tid);
    CP_COMMIT();
    gemm_issue_loads(A, B, m0, n0, 32, sA0 + GBUF * 4, sB0 + GBUF * 4, tid);
    CP_COMMIT();

    const int nk = CH / 32;
    int stage = 0;
    for (int ki = 0; ki < nk; ki++) {
        if (ki + 1 < nk) { CP_WAIT(1); } else { CP_WAIT(0); }
        __syncthreads();   // slab ki visible to all; all warps done with slab ki-1

        const uint32_t Ab = sA0 + stage * GBUF * 4;
        const uint32_t Bb = sB0 + stage * GBUF * 4;

        uint32_t bf[4][4];
#pragma unroll
        for (int kq = 0; kq < 4; kq++) {
            if ((kq & 1) == 0) {
#pragma unroll
                for (int nt = 0; nt < 4; nt++)
                    LDM_X4(bf[nt], Bb + b_lm + nt * (8 * GS * 4) + (kq >> 1) * 64);
            }
#pragma unroll
            for (int mt = 0; mt < 4; mt++) {
                uint32_t af[4];
                LDM_X4(af, Ab + a_lm + mt * (16 * GS * 4) + kq * 32);
#pragma unroll
                for (int nt = 0; nt < 4; nt++)
                    MMA_TF32(acc[mt][nt], af, &bf[nt][(kq & 1) * 2]);
            }
        }

        // Refill the stage vacated at iteration ki-1 (safe: all warps passed
        // this iteration's barrier only after finishing compute(ki-1)).
        if (ki + 2 < nk) {
            int ns = stage + 2 >= NSTAGE ? stage + 2 - NSTAGE : stage + 2;
            gemm_issue_loads(A, B, m0, n0, (ki + 2) * 32,
                             sA0 + ns * GBUF * 4, sB0 + ns * GBUF * 4, tid);
            CP_COMMIT();
        }
        stage = (stage + 1 == NSTAGE) ? 0 : stage + 1;
    }
}

// ---------------------------------------------------------------------------
// Kernel 1: QKV GEMM; writes q,k [b,h,t,d] and v [b,h,d,t], tf32-rounded,
// softmax scale folded into q.
// ---------------------------------------------------------------------------
__global__ __launch_bounds__(256) void qkv_gemm_kernel(
    const float* __restrict__ bias)
{
    extern __shared__ float smg[];
    const uint32_t sbase = smem_u32(smg);
    const int tid = threadIdx.x;
    const int m0 = blockIdx.y * 128;
    const int n0 = blockIdx.x * 128;

    float acc[4][4][4];
#pragma unroll
    for (int i = 0; i < 4; i++)
#pragma unroll
        for (int j = 0; j < 4; j++)
#pragma unroll
            for (int q = 0; q < 4; q++) acc[i][j][q] = 0.f;

    tf32_gemm_tile(g_x, g_wa, m0, n0, acc, sbase, tid);

    const int lane = tid & 31;
    const int wid  = tid >> 5;
    const int wm   = wid & 1;
    const int wn   = wid >> 1;
    const int lr   = lane >> 2;
    const int lc   = lane & 3;

    const int sec = n0 >> 10;  // 0=q 1=k 2=v
    const float scale = (sec == 0) ? 0.125f : 1.0f;

#pragma unroll
    for (int mt = 0; mt < 4; mt++) {
        int r0 = m0 + wm * 64 + mt * 16 + lr;
        int bb = r0 >> 11;
        int t  = r0 & (SEQ - 1);
#pragma unroll
        for (int nt = 0; nt < 4; nt++) {
            int c0 = n0 + wn * 32 + nt * 8 + lc * 2;
            float b0 = bias[c0], b1 = bias[c0 + 1];
            int n1 = c0 & (CH - 1);
            int h  = n1 >> 6;
            int d  = n1 & 63;
            float v00 = to_tf32((acc[mt][nt][0] + b0) * scale);
            float v01 = to_tf32((acc[mt][nt][1] + b1) * scale);
            float v10 = to_tf32((acc[mt][nt][2] + b0) * scale);
            float v11 = to_tf32((acc[mt][nt][3] + b1) * scale);
            if (sec < 2) {
                float* dst = (sec == 0) ? g_q : g_k;
                size_t base = ((size_t)((bb * NHEAD + h) * SEQ + t)) * HDIM + d;
                *reinterpret_cast<float2*>(&dst[base]) = make_float2(v00, v01);
                *reinterpret_cast<float2*>(&dst[base + 8 * HDIM]) =
                    make_float2(v10, v11);
            } else {
                // v transposed: [b,h,d,t]
                size_t base = ((size_t)((bb * NHEAD + h) * HDIM + d)) * SEQ + t;
                g_v[base]           = v00;
                g_v[base + SEQ]     = v01;   // d+1
                g_v[base + 8]       = v10;   // t+8
                g_v[base + SEQ + 8] = v11;
            }
        }
    }
}

// ---------------------------------------------------------------------------
// Kernel 3: output projection
// ---------------------------------------------------------------------------
__global__ __launch_bounds__(256) void proj_gemm_kernel(
    const float* __restrict__ bias, float* __restrict__ out)
{
    extern __shared__ float smg[];
    const uint32_t sbase = smem_u32(smg);
    const int tid = threadIdx.x;
    const int m0 = blockIdx.y * 128;
    const int n0 = blockIdx.x * 128;

    float acc[4][4][4];
#pragma unroll
    for (int i = 0; i < 4; i++)
#pragma unroll
        for (int j = 0; j < 4; j++)
#pragma unroll
            for (int q = 0; q < 4; q++) acc[i][j][q] = 0.f;

    tf32_gemm_tile(g_att, g_wp, m0, n0, acc, sbase, tid);

    const int lane = tid & 31;
    const int wid  = tid >> 5;
    const int wm   = wid & 1;
    const int wn   = wid >> 1;
    const int lr   = lane >> 2;
    const int lc   = lane & 3;

#pragma unroll
    for (int mt = 0; mt < 4; mt++) {
        int r0 = m0 + wm * 64 + mt * 16 + lr;
#pragma unroll
        for (int nt = 0; nt < 4; nt++) {
            int c0 = n0 + wn * 32 + nt * 8 + lc * 2;
            float b0 = bias[c0], b1 = bias[c0 + 1];
            *reinterpret_cast<float2*>(&out[(size_t)r0 * CH + c0]) =
                make_float2(acc[mt][nt][0] + b0, acc[mt][nt][1] + b1);
            *reinterpret_cast<float2*>(&out[(size_t)(r0 + 8) * CH + c0]) =
                make_float2(acc[mt][nt][2] + b0, acc[mt][nt][3] + b1);
        }
    }
}

// ---------------------------------------------------------------------------
// Kernel 2: causal flash attention, TF32 mma.sync + ldmatrix fragments,
// cp.async double-buffered K/V. Block: 128 q x 64 kv; 8 warps x 16 q rows.
// (unchanged from round 6 — proven)
// ---------------------------------------------------------------------------
#define AST 68                     // attention smem row stride (floats)
#define KV_BUF (64 * AST)
#define ATTN_SMEM ((128 * AST + 4 * KV_BUF) * (int)sizeof(float))

__device__ __forceinline__ void attn_issue_kv(
    const float* __restrict__ kp, const float* __restrict__ vp,
    int k0, uint32_t sK, uint32_t sV, int tid)
{
#pragma unroll
    for (int it = 0; it < 4; it++) {
        int idx = it * 256 + tid;
        int row = idx >> 4;
        int c4  = (idx & 15) * 4;
        CP_ASYNC16(sK + row * (AST * 4) + c4 * 4,
                   kp + (size_t)(k0 + row) * HDIM + c4);
        CP_ASYNC16(sV + row * (AST * 4) + c4 * 4,
                   vp + (size_t)row * SEQ + k0 + c4);
    }
}

__global__ __launch_bounds__(256) void attn_kernel()
{
    extern __shared__ float sm[];
    const uint32_t sbase = smem_u32(sm);
    const uint32_t sQs = sbase;
    const uint32_t sKs = sbase + 128 * AST * 4;
    const uint32_t sVs = sKs + 2 * KV_BUF * 4;

    const int tid   = threadIdx.x;
    const int lane  = tid & 31;
    const int wq    = tid >> 5;
    const int lr    = lane >> 2;
    const int lc    = lane & 3;
    const int lane8 = lane & 7;
    const int laneh = (lane >> 3) & 1;
    const int laneq = lane >> 4;

    const int qt = (int)gridDim.x - 1 - (int)blockIdx.x;  // big tiles first
    const int bh = blockIdx.y;
    const int q0 = qt * 128;

    const float* qp = g_q + (size_t)bh * SEQ * HDIM;
    const float* kp = g_k + (size_t)bh * SEQ * HDIM;
    const float* vp = g_v + (size_t)bh * HDIM * SEQ;

    const uint32_t q_lm = sQs +
        ((wq * 16 + lane8 + laneh * 8) * AST + laneq * 4) * 4;
    const uint32_t k_lm = (lane8 * AST + (lane >> 3) * 4) * 4;
    const uint32_t p_lm = ((lane8 + laneh * 8) * AST + laneq * 4) * 4;
    const uint32_t v_lm = ((laneq * 8 + lane8) * AST + laneh * 4) * 4;

#pragma unroll
    for (int it = 0; it < 8; it++) {
        int idx = it * 256 + tid;
        int row = idx >> 4;
        int c4  = (idx & 15) * 4;
        CP_ASYNC16(sQs + row * (AST * 4) + c4 * 4,
                   qp + (size_t)(q0 + row) * HDIM + c4);
    }
    attn_issue_kv(kp, vp, 0, sKs, sVs, tid);
    CP_COMMIT();

    uint32_t qf[8][4];
    const uint32_t sPt = sQs + wq * 16 * AST * 4;   // per-warp 16x64 slab
    float* Pt = sm + wq * 16 * AST;

    float o[8][4] = {};
    float m0v = -1e30f, m1v = -1e30f;
    float l0v = 0.f, l1v = 0.f;

    const int nkt  = 2 * qt + 2;
    const int r_hi = q0 + wq * 16 + 15;

    for (int kt = 0; kt < nkt; kt++) {
        const int k0 = kt * 64;
        if (kt + 1 < nkt) {
            attn_issue_kv(kp, vp, (kt + 1) * 64,
                          sKs + ((kt + 1) & 1) * KV_BUF * 4,
                          sVs + ((kt + 1) & 1) * KV_BUF * 4, tid);
            CP_COMMIT();
            CP_WAIT(1);
        } else {
            CP_WAIT(0);
        }
        __syncthreads();

        if (kt == 0) {
#pragma unroll
            for (int s = 0; s < 8; s++)
                LDM_X4(qf[s], q_lm + s * 32);
        }

        if (k0 <= r_hi) {
            const uint32_t Kb = sKs + (kt & 1) * KV_BUF * 4;
            const uint32_t Vb = sVs + (kt & 1) * KV_BUF * 4;

            float sacc[8][4];
#pragma unroll
            for (int nt = 0; nt < 8; nt++)
#pragma unroll
                for (int q = 0; q < 4; q++) sacc[nt][q] = 0.f;

#pragma unroll
            for (int s2 = 0; s2 < 4; s2++) {
                uint32_t bf[8][4];
#pragma unroll
                for (int nt = 0; nt < 8; nt++)
                    LDM_X4(bf[nt], Kb + k_lm + nt * (8 * AST * 4) + s2 * 64);
#pragma unroll
                for (int sub = 0; sub < 2; sub++)
#pragma unroll
                    for (int nt = 0; nt < 8; nt++)
                        MMA_TF32(sacc[nt], qf[2 * s2 + sub], &bf[nt][sub * 2]);
            }

            if (kt >= 2 * qt) {
                int r0g = q0 + wq * 16 + lr;
#pragma unroll
                for (int nt = 0; nt < 8; nt++) {
                    int c0g = k0 + nt * 8 + 2 * lc;
                    if (c0g     > r0g)     sacc[nt][0] = -1e30f;
                    if (c0g + 1 > r0g)     sacc[nt][1] = -1e30f;
                    if (c0g     > r0g + 8) sacc[nt][2] = -1e30f;
                    if (c0g + 1 > r0g + 8) sacc[nt][3] = -1e30f;
                }
            }

            float rm0 = -1e30f, rm1 = -1e30f;
#pragma unroll
            for (int nt = 0; nt < 8; nt++) {
                rm0 = fmaxf(rm0, fmaxf(sacc[nt][0], sacc[nt][1]));
                rm1 = fmaxf(rm1, fmaxf(sacc[nt][2], sacc[nt][3]));
            }
            rm0 = fmaxf(rm0, __shfl_xor_sync(0xffffffffu, rm0, 1));
            rm0 = fmaxf(rm0, __shfl_xor_sync(0xffffffffu, rm0, 2));
            rm1 = fmaxf(rm1, __shfl_xor_sync(0xffffffffu, rm1, 1));
            rm1 = fmaxf(rm1, __shfl_xor_sync(0xffffffffu, rm1, 2));

            float mn0 = fmaxf(m0v, rm0);
            float mn1 = fmaxf(m1v, rm1);
            float cr0 = __expf(m0v - mn0);
            float cr1 = __expf(m1v - mn1);
            m0v = mn0; m1v = mn1;

            float rs0 = 0.f, rs1 = 0.f;
#pragma unroll
            for (int nt = 0; nt < 8; nt++) {
                sacc[nt][0] = __expf(sacc[nt][0] - mn0);
                sacc[nt][1] = __expf(sacc[nt][1] - mn0);
                sacc[nt][2] = __expf(sacc[nt][2] - mn1);
                sacc[nt][3] = __expf(sacc[nt][3] - mn1);
                rs0 += sacc[nt][0] + sacc[nt][1];
                rs1 += sacc[nt][2] + sacc[nt][3];
            }
            rs0 += __shfl_xor_sync(0xffffffffu, rs0, 1);
            rs0 += __shfl_xor_sync(0xffffffffu, rs0, 2);
            rs1 += __shfl_xor_sync(0xffffffffu, rs1, 1);
            rs1 += __shfl_xor_sync(0xffffffffu, rs1, 2);
            l0v = l0v * cr0 + rs0;
            l1v = l1v * cr1 + rs1;
#pragma unroll
            for (int nt = 0; nt < 8; nt++) {
                o[nt][0] *= cr0; o[nt][1] *= cr0;
                o[nt][2] *= cr1; o[nt][3] *= cr1;
            }

#pragma unroll
            for (int nt = 0; nt < 8; nt++) {
                *reinterpret_cast<float2*>(&Pt[lr * AST + nt * 8 + 2 * lc]) =
                    make_float2(to_tf32(sacc[nt][0]), to_tf32(sacc[nt][1]));
                *reinterpret_cast<float2*>(&Pt[(lr + 8) * AST + nt * 8 + 2 * lc]) =
                    make_float2(to_tf32(sacc[nt][2]), to_tf32(sacc[nt][3]));
            }
            __syncwarp();

#pragma unroll
            for (int s = 0; s < 8; s++) {
                uint32_t a[4];
                LDM_X4(a, sPt + p_lm + s * 32);
#pragma unroll
                for (int dp = 0; dp < 4; dp++) {
                    uint32_t b[4];
                    LDM_X4(b, Vb + v_lm + dp * (16 * AST * 4) + s * 32);
                    MMA_TF32(o[2 * dp],     a, &b[0]);
                    MMA_TF32(o[2 * dp + 1], a, &b[2]);
                }
            }
            __syncwarp();
        }
        __syncthreads();
    }

    const int b = bh >> 4, h = bh & 15;
    const int r0g = q0 + wq * 16 + lr;
    const float inv0 = 1.0f / l0v;
    const float inv1 = 1.0f / l1v;
#pragma unroll
    for (int nt = 0; nt < 8; nt++) {
        int cg = h * 64 + nt * 8 + 2 * lc;
        *reinterpret_cast<float2*>(&g_att[(size_t)(b * SEQ + r0g) * CH + cg]) =
            make_float2(to_tf32(o[nt][0] * inv0), to_tf32(o[nt][1] * inv0));
        *reinterpret_cast<float2*>(&g_att[(size_t)(b * SEQ + r0g + 8) * CH + cg]) =
            make_float2(to_tf32(o[nt][2] * inv1), to_tf32(o[nt][3] * inv1));
    }
}

// ---------------------------------------------------------------------------
extern "C" void kernel_launch(void* const* d_in, const int* in_sizes, int n_in,
                              void* d_out, int out_size)
{
    const float* x      = (const float*)d_in[0];
    const float* w_attn = (const float*)d_in[1];
    const float* b_attn = (const float*)d_in[2];
    const float* w_proj = (const float*)d_in[3];
    const float* b_proj = (const float*)d_in[4];
    float* out = (float*)d_out;

    cudaFuncSetAttribute(qkv_gemm_kernel,
                         cudaFuncAttributeMaxDynamicSharedMemorySize, GEMM_SMEM);
    cudaFuncSetAttribute(proj_gemm_kernel,
                         cudaFuncAttributeMaxDynamicSharedMemorySize, GEMM_SMEM);
    cudaFuncSetAttribute(attn_kernel,
                         cudaFuncAttributeMaxDynamicSharedMemorySize, ATTN_SMEM);

    // 0) tf32-round x; transpose+round weights to [N][K]
    cvt_x_kernel<<<(BATCH * SEQ * CH / 4 + 255) / 256, 256>>>(x,
        BATCH * SEQ * CH / 4);
    cvt_T_kernel<<<dim3(3 * CH / 32, CH / 32), dim3(32, 8)>>>(w_attn, 1, 3 * CH);
    cvt_T_kernel<<<dim3(CH / 32, CH / 32), dim3(32, 8)>>>(w_proj, 2, CH);

    // 1) QKV GEMM: grid (3072/128, 8192/128)
    qkv_gemm_kernel<<<dim3(24, 64), 256, GEMM_SMEM>>>(b_attn);

    // 2) Attention: grid (16 q-tiles, B*NH)
    attn_kernel<<<dim3(16, BATCH * NHEAD), 256, ATTN_SMEM>>>();

    // 3) Projection: grid (1024/128, 8192/128)
    proj_gemm_kernel<<<dim3(8, 64), 256, GEMM_SMEM>>>(b_proj, out);
}